// round 1
// baseline (speedup 1.0000x reference)
#include <cuda_runtime.h>
#include <cstdint>

typedef unsigned long long ull;

// ---- packed f32x2 helpers (sm_100+/sm_103a: FFMA2 via PTX fma.rn.f32x2) ----
__device__ __forceinline__ ull pk2(float a, float b){
  ull r; asm("mov.b64 %0, {%1,%2};" : "=l"(r) : "f"(a), "f"(b)); return r;
}
__device__ __forceinline__ void fma2(ull& d, ull a, ull b){
  asm("fma.rn.f32x2 %0, %1, %2, %0;" : "+l"(d) : "l"(a), "l"(b));
}
__device__ __forceinline__ void mul2(ull& d, ull a){
  asm("mul.rn.f32x2 %0, %0, %1;" : "+l"(d) : "l"(a));
}
__device__ __forceinline__ float2 upk2(ull v){
  float x, y; asm("mov.b64 {%0,%1}, %2;" : "=f"(x), "=f"(y) : "l"(v));
  float2 f; f.x = x; f.y = y; return f;
}

// ---- scratch (device globals: allocation-free rule) ----
#define MROWS 8192
#define DDIM  1024
__device__ float g_xl[MROWS*DDIM];
__device__ float g_q [MROWS*DDIM];
__device__ float g_k [MROWS*DDIM];
__device__ float g_v [MROWS*DDIM];
__device__ float g_o [MROWS*DDIM];
__device__ float g_x2[MROWS*DDIM];
__device__ float g_h [MROWS*4*DDIM];

// ---------------- LayerNorm: one block per row, D=1024 ----------------
__global__ __launch_bounds__(256) void ln1024(
    const float* __restrict__ x, const float* __restrict__ g,
    const float* __restrict__ bt, float* __restrict__ y)
{
  int row = blockIdx.x;
  const float4* xr = (const float4*)(x + (size_t)row * 1024);
  float4 v = xr[threadIdx.x];
  float s = v.x + v.y + v.z + v.w;
  float q = v.x*v.x + v.y*v.y + v.z*v.z + v.w*v.w;
  #pragma unroll
  for (int off = 16; off; off >>= 1){
    s += __shfl_xor_sync(0xffffffffu, s, off);
    q += __shfl_xor_sync(0xffffffffu, q, off);
  }
  __shared__ float ss[8], qs[8];
  int w = threadIdx.x >> 5;
  if ((threadIdx.x & 31) == 0){ ss[w] = s; qs[w] = q; }
  __syncthreads();
  s = ss[0]+ss[1]+ss[2]+ss[3]+ss[4]+ss[5]+ss[6]+ss[7];
  q = qs[0]+qs[1]+qs[2]+qs[3]+qs[4]+qs[5]+qs[6]+qs[7];
  float mu   = s * (1.0f/1024.0f);
  float var  = q * (1.0f/1024.0f) - mu*mu;
  float rstd = rsqrtf(var + 1e-5f);
  int c = threadIdx.x * 4;
  float4 gg = *(const float4*)(g  + c);
  float4 bb = *(const float4*)(bt + c);
  float4 o;
  o.x = (v.x-mu)*rstd*gg.x + bb.x;
  o.y = (v.y-mu)*rstd*gg.y + bb.y;
  o.z = (v.z-mu)*rstd*gg.z + bb.z;
  o.w = (v.w-mu)*rstd*gg.w + bb.w;
  ((float4*)(y + (size_t)row*1024))[threadIdx.x] = o;
}

// ---------------- SGEMM 128x128 tile, BK=16, f32x2 packed ----------------
// C[M,N] = A[M,K] @ B[K,N] (+bias) (relu?) (+res)
__global__ __launch_bounds__(256) void sgemm128(
    const float* __restrict__ A, const float* __restrict__ B,
    const float* __restrict__ bias, const float* __restrict__ res,
    float* __restrict__ C, int M, int N, int K, int relu)
{
  __shared__ __align__(16) float As[16][128];
  __shared__ __align__(16) float Bs[16][128];
  const int tid = threadIdx.x;
  const int tx = tid & 15, ty = tid >> 4;
  const int row0 = blockIdx.y * 128, col0 = blockIdx.x * 128;

  const int lar = tid & 127, lak = (tid >> 7) * 8;  // A: 128 rows x 16 k
  const int lbk = tid >> 4,  lbc = (tid & 15) * 4;  // B: 16 k x 128 cols
  const float* Ap = A + (size_t)(row0 + lar) * K + lak;
  const float* Bp = B + (size_t)lbk * N + col0 + lbc;

  ull acc[8][4];
  #pragma unroll
  for (int i = 0; i < 8; i++)
    #pragma unroll
    for (int j = 0; j < 4; j++) acc[i][j] = 0ULL;

  for (int k0 = 0; k0 < K; k0 += 16){
    float4 a0 = *(const float4*)(Ap);
    float4 a1 = *(const float4*)(Ap + 4);
    float4 b0 = *(const float4*)(Bp);
    float4 b1 = *(const float4*)(Bp + 64);
    __syncthreads();
    As[lak+0][lar]=a0.x; As[lak+1][lar]=a0.y; As[lak+2][lar]=a0.z; As[lak+3][lar]=a0.w;
    As[lak+4][lar]=a1.x; As[lak+5][lar]=a1.y; As[lak+6][lar]=a1.z; As[lak+7][lar]=a1.w;
    *(float4*)&Bs[lbk][lbc]      = b0;
    *(float4*)&Bs[lbk][lbc + 64] = b1;
    __syncthreads();
    #pragma unroll
    for (int kk = 0; kk < 16; kk++){
      float4 va0 = *(const float4*)&As[kk][ty*4];
      float4 va1 = *(const float4*)&As[kk][64 + ty*4];
      float4 vb0 = *(const float4*)&Bs[kk][tx*4];
      float4 vb1 = *(const float4*)&Bs[kk][64 + tx*4];
      ull bb0 = pk2(vb0.x, vb0.y), bb1 = pk2(vb0.z, vb0.w);
      ull bb2 = pk2(vb1.x, vb1.y), bb3 = pk2(vb1.z, vb1.w);
      float av[8] = {va0.x,va0.y,va0.z,va0.w,va1.x,va1.y,va1.z,va1.w};
      #pragma unroll
      for (int i = 0; i < 8; i++){
        ull aa = pk2(av[i], av[i]);
        fma2(acc[i][0], aa, bb0); fma2(acc[i][1], aa, bb1);
        fma2(acc[i][2], aa, bb2); fma2(acc[i][3], aa, bb3);
      }
    }
    Ap += 16; Bp += (size_t)16 * N;
  }

  #pragma unroll
  for (int ih = 0; ih < 2; ih++)
  #pragma unroll
  for (int i = 0; i < 4; i++){
    int r = row0 + ih*64 + ty*4 + i;
    #pragma unroll
    for (int jh = 0; jh < 2; jh++){
      int c = col0 + jh*64 + tx*4;
      float2 p0 = upk2(acc[ih*4 + i][jh*2 + 0]);
      float2 p1 = upk2(acc[ih*4 + i][jh*2 + 1]);
      float4 o = make_float4(p0.x, p0.y, p1.x, p1.y);
      if (bias){
        float4 bv = *(const float4*)(bias + c);
        o.x += bv.x; o.y += bv.y; o.z += bv.z; o.w += bv.w;
      }
      if (relu){
        o.x = fmaxf(o.x, 0.f); o.y = fmaxf(o.y, 0.f);
        o.z = fmaxf(o.z, 0.f); o.w = fmaxf(o.w, 0.f);
      }
      if (res){
        float4 rv = *(const float4*)(res + (size_t)r * N + c);
        o.x += rv.x; o.y += rv.y; o.z += rv.z; o.w += rv.w;
      }
      *(float4*)(C + (size_t)r * N + c) = o;
    }
  }
}

// ---------------- Flash attention, Br=Bc=64, C=64, fp32 ----------------
// q,k,v,o in row-major [B*S, D] layout (head h occupies cols h*64..h*64+63).
// scores = (q . k) * sqrt(C)=8 (faithful to reference quirk), softmax over S.
__global__ __launch_bounds__(256) void attn64(
    const float* __restrict__ Q, const float* __restrict__ K,
    const float* __restrict__ V, float* __restrict__ O)
{
  __shared__ float Qt[64*64];    // Qt[c][r]  (transposed)
  __shared__ float KtPs[64*64];  // Kt[c][j] during S-gemm; swizzled P[r][j] after
  __shared__ float Vs[64*64];    // Vs[j][c]  (natural)
  const int tid = threadIdx.x;
  const int tx = tid & 15, ty = tid >> 4;
  const int b = blockIdx.z, h = blockIdx.y, q0 = blockIdx.x * 64;
  const int S = 2048, D = 1024;
  const size_t base = ((size_t)b * S) * D + h * 64;

  { // load Q tile, transposed into smem
    int r = tid >> 2, c4 = (tid & 3) * 16;
    const float* qp = Q + base + (size_t)(q0 + r) * D + c4;
    #pragma unroll
    for (int u = 0; u < 4; u++){
      float4 t = *(const float4*)(qp + 4*u);
      Qt[(c4+4*u+0)*64 + r] = t.x;
      Qt[(c4+4*u+1)*64 + r] = t.y;
      Qt[(c4+4*u+2)*64 + r] = t.z;
      Qt[(c4+4*u+3)*64 + r] = t.w;
    }
  }

  float m[4] = {-1e30f, -1e30f, -1e30f, -1e30f};
  float l[4] = {0.f, 0.f, 0.f, 0.f};
  ull oacc[4][2] = {{0,0},{0,0},{0,0},{0,0}};

  for (int jt = 0; jt < 32; jt++){
    int j0 = jt * 64;
    __syncthreads();  // prior tile fully consumed (and Qt ready on iter 0)
    { // load K (transposed) and V (natural) tiles
      int r = tid >> 2, c4 = (tid & 3) * 16;
      const float* kp = K + base + (size_t)(j0 + r) * D + c4;
      const float* vp = V + base + (size_t)(j0 + r) * D + c4;
      #pragma unroll
      for (int u = 0; u < 4; u++){
        float4 t = *(const float4*)(kp + 4*u);
        KtPs[(c4+4*u+0)*64 + r] = t.x;
        KtPs[(c4+4*u+1)*64 + r] = t.y;
        KtPs[(c4+4*u+2)*64 + r] = t.z;
        KtPs[(c4+4*u+3)*64 + r] = t.w;
        float4 w = *(const float4*)(vp + 4*u);
        *(float4*)&Vs[r*64 + c4 + 4*u] = w;
      }
    }
    __syncthreads();

    // S = Q @ K^T (thread: 4 rows x 4 cols, packed pairs)
    ull sacc[4][2] = {{0,0},{0,0},{0,0},{0,0}};
    #pragma unroll 16
    for (int c = 0; c < 64; c++){
      float4 qa = *(const float4*)&Qt[c*64 + ty*4];
      float4 kb = *(const float4*)&KtPs[c*64 + tx*4];
      ull b0 = pk2(kb.x, kb.y), b1 = pk2(kb.z, kb.w);
      ull a;
      a = pk2(qa.x, qa.x); fma2(sacc[0][0], a, b0); fma2(sacc[0][1], a, b1);
      a = pk2(qa.y, qa.y); fma2(sacc[1][0], a, b0); fma2(sacc[1][1], a, b1);
      a = pk2(qa.z, qa.z); fma2(sacc[2][0], a, b0); fma2(sacc[2][1], a, b1);
      a = pk2(qa.w, qa.w); fma2(sacc[3][0], a, b0); fma2(sacc[3][1], a, b1);
    }

    float p[4][4];
    #pragma unroll
    for (int i = 0; i < 4; i++){
      float2 lo = upk2(sacc[i][0]), hi = upk2(sacc[i][1]);
      p[i][0] = lo.x * 8.f; p[i][1] = lo.y * 8.f;
      p[i][2] = hi.x * 8.f; p[i][3] = hi.y * 8.f;
    }

    // online softmax: row reductions across the 16 tx lanes (half-warp shfl)
    #pragma unroll
    for (int i = 0; i < 4; i++){
      float mx = fmaxf(fmaxf(p[i][0], p[i][1]), fmaxf(p[i][2], p[i][3]));
      #pragma unroll
      for (int off = 8; off; off >>= 1)
        mx = fmaxf(mx, __shfl_xor_sync(0xffffffffu, mx, off));
      float mn = fmaxf(m[i], mx);
      float al = __expf(m[i] - mn);
      float rs = 0.f;
      #pragma unroll
      for (int jj = 0; jj < 4; jj++){
        p[i][jj] = __expf(p[i][jj] - mn);
        rs += p[i][jj];
      }
      #pragma unroll
      for (int off = 8; off; off >>= 1)
        rs += __shfl_xor_sync(0xffffffffu, rs, off);
      l[i] = l[i] * al + rs;
      m[i] = mn;
      ull av = pk2(al, al);
      mul2(oacc[i][0], av); mul2(oacc[i][1], av);
    }

    __syncthreads();  // everyone done reading Kt -> reuse as P (bank-swizzled)
    #pragma unroll
    for (int i = 0; i < 4; i++){
      int r = ty*4 + i;
      #pragma unroll
      for (int jj = 0; jj < 4; jj++){
        int jcol = (tx*4 + jj + r) & 63;  // per-row rotate: conflict-free reads
        KtPs[r*64 + jcol] = p[i][jj];
      }
    }
    __syncthreads();

    // O += P @ V
    #pragma unroll 16
    for (int j = 0; j < 64; j++){
      float4 vb = *(const float4*)&Vs[j*64 + tx*4];
      ull b0 = pk2(vb.x, vb.y), b1 = pk2(vb.z, vb.w);
      #pragma unroll
      for (int i = 0; i < 4; i++){
        int r = ty*4 + i;
        float pr = KtPs[r*64 + ((j + r) & 63)];
        ull aa = pk2(pr, pr);
        fma2(oacc[i][0], aa, b0); fma2(oacc[i][1], aa, b1);
      }
    }
  }

  #pragma unroll
  for (int i = 0; i < 4; i++){
    float inv = 1.0f / l[i];
    float2 lo = upk2(oacc[i][0]), hi = upk2(oacc[i][1]);
    float4 o4 = make_float4(lo.x*inv, lo.y*inv, hi.x*inv, hi.y*inv);
    int r = q0 + ty*4 + i;
    *(float4*)(O + base + (size_t)r * D + tx*4) = o4;
  }
}

// ---------------- launch ----------------
extern "C" void kernel_launch(void* const* d_in, const int* in_sizes, int n_in,
                              void* d_out, int out_size)
{
  (void)in_sizes; (void)n_in; (void)out_size;
  const float* x   = (const float*)d_in[0];
  // d_in[1] = src_mask (unused by reference)
  const float* Wk  = (const float*)d_in[2];
  const float* Wq  = (const float*)d_in[3];
  const float* Wv  = (const float*)d_in[4];
  const float* Wfc = (const float*)d_in[5];
  const float* bfc = (const float*)d_in[6];
  const float* g1  = (const float*)d_in[7];
  const float* b1  = (const float*)d_in[8];
  const float* g2  = (const float*)d_in[9];
  const float* b2  = (const float*)d_in[10];
  const float* W1  = (const float*)d_in[11];
  const float* bf1 = (const float*)d_in[12];
  const float* W2  = (const float*)d_in[13];
  const float* bf2 = (const float*)d_in[14];
  float* out = (float*)d_out;

  float *xl, *q, *k, *v, *o, *x2, *h;
  cudaGetSymbolAddress((void**)&xl, g_xl);
  cudaGetSymbolAddress((void**)&q,  g_q);
  cudaGetSymbolAddress((void**)&k,  g_k);
  cudaGetSymbolAddress((void**)&v,  g_v);
  cudaGetSymbolAddress((void**)&o,  g_o);
  cudaGetSymbolAddress((void**)&x2, g_x2);
  cudaGetSymbolAddress((void**)&h,  g_h);

  const int M = 8192, D = 1024;
  dim3 gD(D/128, M/128);        // (8, 64)
  dim3 gF(4*D/128, M/128);      // (32, 64)

  ln1024<<<M, 256>>>(x, g1, b1, xl);                                  // xl = LN1(x)
  sgemm128<<<gD, 256>>>(xl, Wq, nullptr, nullptr, q, M, D, D, 0);     // q
  sgemm128<<<gD, 256>>>(xl, Wk, nullptr, nullptr, k, M, D, D, 0);     // k
  sgemm128<<<gD, 256>>>(xl, Wv, nullptr, nullptr, v, M, D, D, 0);     // v
  attn64<<<dim3(32, 16, 4), 256>>>(q, k, v, o);                       // o = attn
  sgemm128<<<gD, 256>>>(o, Wfc, bfc, x, x2, M, D, D, 0);              // x2 = o@Wfc+bfc+x
  ln1024<<<M, 256>>>(x2, g2, b2, xl);                                 // xl = LN2(x2)
  sgemm128<<<gF, 256>>>(xl, W1, bf1, nullptr, h, M, 4*D, D, 1);       // h = relu(xl@W1+bf1)
  sgemm128<<<gD, 256>>>(h, W2, bf2, x2, out, M, D, 4*D, 0);           // out = h@W2+bf2+x2
}

// round 3
// speedup vs baseline: 1.7424x; 1.7424x over previous
#include <cuda_runtime.h>
#include <cuda_bf16.h>
#include <cstdint>

typedef unsigned long long ull;

// ---- packed f32x2 helpers (attention kernel) ----
__device__ __forceinline__ ull pk2(float a, float b){
  ull r; asm("mov.b64 %0, {%1,%2};" : "=l"(r) : "f"(a), "f"(b)); return r;
}
__device__ __forceinline__ void fma2(ull& d, ull a, ull b){
  asm("fma.rn.f32x2 %0, %1, %2, %0;" : "+l"(d) : "l"(a), "l"(b));
}
__device__ __forceinline__ void mul2(ull& d, ull a){
  asm("mul.rn.f32x2 %0, %0, %1;" : "+l"(d) : "l"(a));
}
__device__ __forceinline__ float2 upk2(ull v){
  float x, y; asm("mov.b64 {%0,%1}, %2;" : "=f"(x), "=f"(y) : "l"(v));
  float2 f; f.x = x; f.y = y; return f;
}

// ---- mma / ldmatrix / cp.async helpers (portable PTX, sm_80+) ----
__device__ __forceinline__ uint32_t s2u(const void* p){
  uint32_t a; asm("{ .reg .u64 t; cvta.to.shared.u64 t, %1; cvt.u32.u64 %0, t; }"
                  : "=r"(a) : "l"(p));
  return a;
}
__device__ __forceinline__ void ldsm4(uint32_t& r0, uint32_t& r1, uint32_t& r2,
                                      uint32_t& r3, uint32_t a){
  asm volatile("ldmatrix.sync.aligned.m8n8.x4.shared.b16 {%0,%1,%2,%3}, [%4];"
               : "=r"(r0), "=r"(r1), "=r"(r2), "=r"(r3) : "r"(a));
}
__device__ __forceinline__ void mma16816(float* d, const uint32_t* a, const uint32_t* b){
  asm volatile(
    "mma.sync.aligned.m16n8k16.row.col.f32.bf16.bf16.f32 "
    "{%0,%1,%2,%3}, {%4,%5,%6,%7}, {%8,%9}, {%0,%1,%2,%3};"
    : "+f"(d[0]), "+f"(d[1]), "+f"(d[2]), "+f"(d[3])
    : "r"(a[0]), "r"(a[1]), "r"(a[2]), "r"(a[3]), "r"(b[0]), "r"(b[1]));
}
__device__ __forceinline__ void cpasync16(uint32_t dst, const void* src){
  asm volatile("cp.async.cg.shared.global [%0], [%1], 16;" :: "r"(dst), "l"(src) : "memory");
}
#define CP_COMMIT() asm volatile("cp.async.commit_group;" ::: "memory")
#define CP_WAIT1()  asm volatile("cp.async.wait_group 1;" ::: "memory")
#define CP_WAIT0()  asm volatile("cp.async.wait_group 0;" ::: "memory")

// SW128 swizzle for 128-byte rows
#define SWZ(o) ((o) ^ (((o) >> 3) & 0x70))

// ======================= scratch (device globals) =======================
#define MR 8192
#define DD 1024
__device__ __nv_bfloat16 g_xlh[MR*DD], g_xll[MR*DD];
__device__ float g_q[MR*DD], g_k[MR*DD], g_v[MR*DD];
__device__ __nv_bfloat16 g_oh[MR*DD], g_ol[MR*DD];
__device__ float g_x2[MR*DD];
__device__ __nv_bfloat16 g_hh[MR*4*DD], g_hl[MR*4*DD];
__device__ __nv_bfloat16 g_wqh[DD*DD], g_wql[DD*DD];
__device__ __nv_bfloat16 g_wkh[DD*DD], g_wkl[DD*DD];
__device__ __nv_bfloat16 g_wvh[DD*DD], g_wvl[DD*DD];
__device__ __nv_bfloat16 g_wfh[DD*DD], g_wfl[DD*DD];
__device__ __nv_bfloat16 g_w1h[4*DD*DD], g_w1l[4*DD*DD];
__device__ __nv_bfloat16 g_w2h[4*DD*DD], g_w2l[4*DD*DD];

// ======================= LayerNorm -> bf16 hi/lo =======================
__global__ __launch_bounds__(256) void ln1024_split(
    const float* __restrict__ x, const float* __restrict__ g,
    const float* __restrict__ bt, __nv_bfloat16* __restrict__ yh,
    __nv_bfloat16* __restrict__ yl)
{
  int row = blockIdx.x;
  const float4* xr = (const float4*)(x + (size_t)row * 1024);
  float4 v = xr[threadIdx.x];
  float s = v.x + v.y + v.z + v.w;
  float q = v.x*v.x + v.y*v.y + v.z*v.z + v.w*v.w;
  #pragma unroll
  for (int off = 16; off; off >>= 1){
    s += __shfl_xor_sync(0xffffffffu, s, off);
    q += __shfl_xor_sync(0xffffffffu, q, off);
  }
  __shared__ float ss[8], qs[8];
  int w = threadIdx.x >> 5;
  if ((threadIdx.x & 31) == 0){ ss[w] = s; qs[w] = q; }
  __syncthreads();
  s = ss[0]+ss[1]+ss[2]+ss[3]+ss[4]+ss[5]+ss[6]+ss[7];
  q = qs[0]+qs[1]+qs[2]+qs[3]+qs[4]+qs[5]+qs[6]+qs[7];
  float mu   = s * (1.0f/1024.0f);
  float var  = q * (1.0f/1024.0f) - mu*mu;
  float rstd = rsqrtf(var + 1e-5f);
  int c = threadIdx.x * 4;
  float4 gg = *(const float4*)(g  + c);
  float4 bb = *(const float4*)(bt + c);
  float o0 = (v.x-mu)*rstd*gg.x + bb.x;
  float o1 = (v.y-mu)*rstd*gg.y + bb.y;
  float o2 = (v.z-mu)*rstd*gg.z + bb.z;
  float o3 = (v.w-mu)*rstd*gg.w + bb.w;
  __nv_bfloat16 h0=__float2bfloat16(o0), h1=__float2bfloat16(o1);
  __nv_bfloat16 h2=__float2bfloat16(o2), h3=__float2bfloat16(o3);
  __nv_bfloat162 ph0; ph0.x=h0; ph0.y=h1;
  __nv_bfloat162 ph1; ph1.x=h2; ph1.y=h3;
  __nv_bfloat162 pl0; pl0.x=__float2bfloat16(o0-__bfloat162float(h0));
                      pl0.y=__float2bfloat16(o1-__bfloat162float(h1));
  __nv_bfloat162 pl1; pl1.x=__float2bfloat16(o2-__bfloat162float(h2));
                      pl1.y=__float2bfloat16(o3-__bfloat162float(h3));
  size_t idx = (size_t)row*1024 + c;
  *(__nv_bfloat162*)(yh+idx)   = ph0; *(__nv_bfloat162*)(yh+idx+2) = ph1;
  *(__nv_bfloat162*)(yl+idx)   = pl0; *(__nv_bfloat162*)(yl+idx+2) = pl1;
}

// ======================= weight transpose + split =======================
// W [K,N] fp32 -> Th/Tl [N,K] bf16
__global__ void transp_split(const float* __restrict__ W,
                             __nv_bfloat16* __restrict__ Th,
                             __nv_bfloat16* __restrict__ Tl, int K, int N)
{
  __shared__ float t[32][33];
  int n0 = blockIdx.x*32, k0 = blockIdx.y*32;
  int tx = threadIdx.x, ty = threadIdx.y; // 32 x 8
  #pragma unroll
  for (int j = 0; j < 4; j++)
    t[ty+8*j][tx] = W[(size_t)(k0+ty+8*j)*N + n0+tx];
  __syncthreads();
  #pragma unroll
  for (int j = 0; j < 4; j++){
    float v = t[tx][ty+8*j];
    __nv_bfloat16 h = __float2bfloat16(v);
    size_t idx = (size_t)(n0+ty+8*j)*K + k0+tx;
    Th[idx] = h;
    Tl[idx] = __float2bfloat16(v - __bfloat162float(h));
  }
}

// ======================= split-bf16 GEMM via mma.sync (HMMA) =======================
// C[M,N] = (Ahi+Alo)[M,K] @ (Bhi+Blo)[N,K]^T  (3-term: hh + hi*lo + lo*hi)
// epilogue: +bias, relu?, +res; out fp32 C or split bf16 (Chi,Clo)
__global__ __launch_bounds__(256) void gemm_mma(
    const __nv_bfloat16* __restrict__ Ahi, const __nv_bfloat16* __restrict__ Alo,
    const __nv_bfloat16* __restrict__ Bhi, const __nv_bfloat16* __restrict__ Blo,
    const float* __restrict__ bias, const float* __restrict__ res,
    float* __restrict__ C, __nv_bfloat16* __restrict__ Chi,
    __nv_bfloat16* __restrict__ Clo,
    int M, int N, int K, int relu, int split)
{
  extern __shared__ __align__(1024) char smem[];
  char* sA = smem;            // 2 x 16384 (128 rows x 64 bf16, SW128)
  char* sB = smem + 32768;    // 2 x 16384
  const int tid = threadIdx.x, lane = tid & 31, wid = tid >> 5;
  const int m0 = blockIdx.y * 128, n0 = blockIdx.x * 128;
  const int wm = (wid >> 1) * 32, wn = (wid & 1) * 64;
  const uint32_t aA0 = s2u(sA), aB0 = s2u(sB);

  const int nck = K >> 6;
  const int nc  = 3 * nck;

  float acc[2][8][4];
  #pragma unroll
  for (int i = 0; i < 2; i++)
    #pragma unroll
    for (int j = 0; j < 8; j++)
      #pragma unroll
      for (int r = 0; r < 4; r++) acc[i][j][r] = 0.f;

  // per-thread ldmatrix source coordinates
  const int rowA = lane & 15;
  const int kbA  = (lane & 16) ? 16 : 0;
  const int rowB = (lane & 7) + ((lane & 16) ? 8 : 0);
  const int kbB  = (lane & 8) ? 16 : 0;

  // per-thread cp.async store offsets (4 x 16B each for A and B)
  uint32_t swoff[4]; int ldr[4], ldc[4];
  #pragma unroll
  for (int i = 0; i < 4; i++){
    int gg = tid + 256*i;
    ldr[i] = gg >> 3; ldc[i] = (gg & 7) * 8;
    uint32_t off = (uint32_t)(ldr[i]*128 + (gg & 7)*16);
    swoff[i] = SWZ(off);
  }

  #define ISSUE(c) do { \
    int _p = (c) / nck, _kk = (c) - _p * nck, _k0 = _kk << 6; \
    const __nv_bfloat16* _Ap = (_p == 2) ? Alo : Ahi; \
    const __nv_bfloat16* _Bp = (_p == 1) ? Blo : Bhi; \
    uint32_t _dA = aA0 + ((c) & 1) * 16384; \
    uint32_t _dB = aB0 + ((c) & 1) * 16384; \
    _Pragma("unroll") \
    for (int _i = 0; _i < 4; _i++){ \
      cpasync16(_dA + swoff[_i], _Ap + (size_t)(m0 + ldr[_i]) * K + _k0 + ldc[_i]); \
      cpasync16(_dB + swoff[_i], _Bp + (size_t)(n0 + ldr[_i]) * K + _k0 + ldc[_i]); \
    } \
    CP_COMMIT(); \
  } while(0)

  ISSUE(0);
  for (int c = 0; c < nc; c++){
    if (c + 1 < nc){ ISSUE(c + 1); CP_WAIT1(); }
    else           { CP_WAIT0(); }
    __syncthreads();
    const uint32_t bA = aA0 + (c & 1) * 16384;
    const uint32_t bB = aB0 + (c & 1) * 16384;
    #pragma unroll
    for (int s = 0; s < 4; s++){
      uint32_t af[2][4];
      #pragma unroll
      for (int mi = 0; mi < 2; mi++){
        uint32_t off = (uint32_t)((wm + mi*16 + rowA)*128 + s*32 + kbA);
        ldsm4(af[mi][0], af[mi][1], af[mi][2], af[mi][3], bA + SWZ(off));
      }
      uint32_t bfr[4][4];
      #pragma unroll
      for (int njp = 0; njp < 4; njp++){
        uint32_t off = (uint32_t)((wn + njp*16 + rowB)*128 + s*32 + kbB);
        ldsm4(bfr[njp][0], bfr[njp][1], bfr[njp][2], bfr[njp][3], bB + SWZ(off));
      }
      #pragma unroll
      for (int mi = 0; mi < 2; mi++)
        #pragma unroll
        for (int nj = 0; nj < 8; nj++)
          mma16816(acc[mi][nj], af[mi], &bfr[nj >> 1][(nj & 1) * 2]);
    }
    __syncthreads();
  }

  // epilogue: c-frag (row=t/4 (+8), col=2*(t%4)) within each m16n8 block
  const int er = lane >> 2, ec = (lane & 3) * 2;
  #pragma unroll
  for (int mi = 0; mi < 2; mi++){
    #pragma unroll
    for (int half = 0; half < 2; half++){
      int row = m0 + wm + mi*16 + er + half*8;
      #pragma unroll
      for (int nj = 0; nj < 8; nj++){
        int col = n0 + wn + nj*8 + ec;
        float v0 = acc[mi][nj][half*2 + 0];
        float v1 = acc[mi][nj][half*2 + 1];
        if (bias){
          float2 bv = *(const float2*)(bias + col);
          v0 += bv.x; v1 += bv.y;
        }
        if (relu){ v0 = fmaxf(v0, 0.f); v1 = fmaxf(v1, 0.f); }
        if (res){
          float2 rv = *(const float2*)(res + (size_t)row*N + col);
          v0 += rv.x; v1 += rv.y;
        }
        size_t idx = (size_t)row*N + col;
        if (split){
          __nv_bfloat16 h0 = __float2bfloat16(v0), h1 = __float2bfloat16(v1);
          __nv_bfloat162 ph; ph.x = h0; ph.y = h1;
          __nv_bfloat162 pl;
          pl.x = __float2bfloat16(v0 - __bfloat162float(h0));
          pl.y = __float2bfloat16(v1 - __bfloat162float(h1));
          *(__nv_bfloat162*)(Chi + idx) = ph;
          *(__nv_bfloat162*)(Clo + idx) = pl;
        } else {
          float2 o; o.x = v0; o.y = v1;
          *(float2*)(C + idx) = o;
        }
      }
    }
  }
  #undef ISSUE
}

// ======================= Flash attention (fp32, FFMA2) =======================
__global__ __launch_bounds__(256) void attn64(
    const float* __restrict__ Q, const float* __restrict__ K,
    const float* __restrict__ V, __nv_bfloat16* __restrict__ Oh,
    __nv_bfloat16* __restrict__ Ol)
{
  __shared__ float Qt[64*64];
  __shared__ float KtPs[64*64];
  __shared__ float Vs[64*64];
  const int tid = threadIdx.x;
  const int tx = tid & 15, ty = tid >> 4;
  const int b = blockIdx.z, h = blockIdx.y, q0 = blockIdx.x * 64;
  const int S = 2048, D = 1024;
  const size_t base = ((size_t)b * S) * D + h * 64;

  {
    int r = tid >> 2, c4 = (tid & 3) * 16;
    const float* qp = Q + base + (size_t)(q0 + r) * D + c4;
    #pragma unroll
    for (int u = 0; u < 4; u++){
      float4 t = *(const float4*)(qp + 4*u);
      Qt[(c4+4*u+0)*64 + r] = t.x;
      Qt[(c4+4*u+1)*64 + r] = t.y;
      Qt[(c4+4*u+2)*64 + r] = t.z;
      Qt[(c4+4*u+3)*64 + r] = t.w;
    }
  }

  float m[4] = {-1e30f, -1e30f, -1e30f, -1e30f};
  float l[4] = {0.f, 0.f, 0.f, 0.f};
  ull oacc[4][2] = {{0,0},{0,0},{0,0},{0,0}};

  for (int jt = 0; jt < 32; jt++){
    int j0 = jt * 64;
    __syncthreads();
    {
      int r = tid >> 2, c4 = (tid & 3) * 16;
      const float* kp = K + base + (size_t)(j0 + r) * D + c4;
      const float* vp = V + base + (size_t)(j0 + r) * D + c4;
      #pragma unroll
      for (int u = 0; u < 4; u++){
        float4 t = *(const float4*)(kp + 4*u);
        KtPs[(c4+4*u+0)*64 + r] = t.x;
        KtPs[(c4+4*u+1)*64 + r] = t.y;
        KtPs[(c4+4*u+2)*64 + r] = t.z;
        KtPs[(c4+4*u+3)*64 + r] = t.w;
        float4 w = *(const float4*)(vp + 4*u);
        *(float4*)&Vs[r*64 + c4 + 4*u] = w;
      }
    }
    __syncthreads();

    ull sacc[4][2] = {{0,0},{0,0},{0,0},{0,0}};
    #pragma unroll 16
    for (int c = 0; c < 64; c++){
      float4 qa = *(const float4*)&Qt[c*64 + ty*4];
      float4 kb = *(const float4*)&KtPs[c*64 + tx*4];
      ull b0 = pk2(kb.x, kb.y), b1 = pk2(kb.z, kb.w);
      ull a;
      a = pk2(qa.x, qa.x); fma2(sacc[0][0], a, b0); fma2(sacc[0][1], a, b1);
      a = pk2(qa.y, qa.y); fma2(sacc[1][0], a, b0); fma2(sacc[1][1], a, b1);
      a = pk2(qa.z, qa.z); fma2(sacc[2][0], a, b0); fma2(sacc[2][1], a, b1);
      a = pk2(qa.w, qa.w); fma2(sacc[3][0], a, b0); fma2(sacc[3][1], a, b1);
    }

    float p[4][4];
    #pragma unroll
    for (int i = 0; i < 4; i++){
      float2 lo = upk2(sacc[i][0]), hi = upk2(sacc[i][1]);
      p[i][0] = lo.x * 8.f; p[i][1] = lo.y * 8.f;
      p[i][2] = hi.x * 8.f; p[i][3] = hi.y * 8.f;
    }

    #pragma unroll
    for (int i = 0; i < 4; i++){
      float mx = fmaxf(fmaxf(p[i][0], p[i][1]), fmaxf(p[i][2], p[i][3]));
      #pragma unroll
      for (int off = 8; off; off >>= 1)
        mx = fmaxf(mx, __shfl_xor_sync(0xffffffffu, mx, off));
      float mn = fmaxf(m[i], mx);
      float al = __expf(m[i] - mn);
      float rs = 0.f;
      #pragma unroll
      for (int jj = 0; jj < 4; jj++){
        p[i][jj] = __expf(p[i][jj] - mn);
        rs += p[i][jj];
      }
      #pragma unroll
      for (int off = 8; off; off >>= 1)
        rs += __shfl_xor_sync(0xffffffffu, rs, off);
      l[i] = l[i] * al + rs;
      m[i] = mn;
      ull av = pk2(al, al);
      mul2(oacc[i][0], av); mul2(oacc[i][1], av);
    }

    __syncthreads();
    #pragma unroll
    for (int i = 0; i < 4; i++){
      int r = ty*4 + i;
      #pragma unroll
      for (int jj = 0; jj < 4; jj++){
        int jcol = (tx*4 + jj + r) & 63;
        KtPs[r*64 + jcol] = p[i][jj];
      }
    }
    __syncthreads();

    #pragma unroll 16
    for (int j = 0; j < 64; j++){
      float4 vb = *(const float4*)&Vs[j*64 + tx*4];
      ull b0 = pk2(vb.x, vb.y), b1 = pk2(vb.z, vb.w);
      #pragma unroll
      for (int i = 0; i < 4; i++){
        int r = ty*4 + i;
        float pr = KtPs[r*64 + ((j + r) & 63)];
        ull aa = pk2(pr, pr);
        fma2(oacc[i][0], aa, b0); fma2(oacc[i][1], aa, b1);
      }
    }
  }

  #pragma unroll
  for (int i = 0; i < 4; i++){
    float inv = 1.0f / l[i];
    float2 lo = upk2(oacc[i][0]), hi = upk2(oacc[i][1]);
    float o0 = lo.x*inv, o1 = lo.y*inv, o2 = hi.x*inv, o3 = hi.y*inv;
    int r = q0 + ty*4 + i;
    size_t idx = base + (size_t)r * D + tx*4;
    __nv_bfloat16 h0=__float2bfloat16(o0), h1=__float2bfloat16(o1);
    __nv_bfloat16 h2=__float2bfloat16(o2), h3=__float2bfloat16(o3);
    __nv_bfloat162 ph0; ph0.x=h0; ph0.y=h1;
    __nv_bfloat162 ph1; ph1.x=h2; ph1.y=h3;
    __nv_bfloat162 pl0; pl0.x=__float2bfloat16(o0-__bfloat162float(h0));
                        pl0.y=__float2bfloat16(o1-__bfloat162float(h1));
    __nv_bfloat162 pl1; pl1.x=__float2bfloat16(o2-__bfloat162float(h2));
                        pl1.y=__float2bfloat16(o3-__bfloat162float(h3));
    *(__nv_bfloat162*)(Oh+idx)   = ph0; *(__nv_bfloat162*)(Oh+idx+2) = ph1;
    *(__nv_bfloat162*)(Ol+idx)   = pl0; *(__nv_bfloat162*)(Ol+idx+2) = pl1;
  }
}

// ======================= launch =======================
extern "C" void kernel_launch(void* const* d_in, const int* in_sizes, int n_in,
                              void* d_out, int out_size)
{
  (void)in_sizes; (void)n_in; (void)out_size;
  const float* x   = (const float*)d_in[0];
  const float* Wk  = (const float*)d_in[2];
  const float* Wq  = (const float*)d_in[3];
  const float* Wv  = (const float*)d_in[4];
  const float* Wfc = (const float*)d_in[5];
  const float* bfc = (const float*)d_in[6];
  const float* g1  = (const float*)d_in[7];
  const float* b1  = (const float*)d_in[8];
  const float* g2  = (const float*)d_in[9];
  const float* b2  = (const float*)d_in[10];
  const float* W1  = (const float*)d_in[11];
  const float* bf1 = (const float*)d_in[12];
  const float* W2  = (const float*)d_in[13];
  const float* bf2 = (const float*)d_in[14];
  float* out = (float*)d_out;

  __nv_bfloat16 *xlh,*xll,*oh,*ol,*hh,*hl;
  __nv_bfloat16 *wqh,*wql,*wkh,*wkl,*wvh,*wvl,*wfh,*wfl,*w1h,*w1l,*w2h,*w2l;
  float *q,*k,*v,*x2;
  cudaGetSymbolAddress((void**)&xlh, g_xlh); cudaGetSymbolAddress((void**)&xll, g_xll);
  cudaGetSymbolAddress((void**)&q, g_q); cudaGetSymbolAddress((void**)&k, g_k);
  cudaGetSymbolAddress((void**)&v, g_v);
  cudaGetSymbolAddress((void**)&oh, g_oh); cudaGetSymbolAddress((void**)&ol, g_ol);
  cudaGetSymbolAddress((void**)&x2, g_x2);
  cudaGetSymbolAddress((void**)&hh, g_hh); cudaGetSymbolAddress((void**)&hl, g_hl);
  cudaGetSymbolAddress((void**)&wqh, g_wqh); cudaGetSymbolAddress((void**)&wql, g_wql);
  cudaGetSymbolAddress((void**)&wkh, g_wkh); cudaGetSymbolAddress((void**)&wkl, g_wkl);
  cudaGetSymbolAddress((void**)&wvh, g_wvh); cudaGetSymbolAddress((void**)&wvl, g_wvl);
  cudaGetSymbolAddress((void**)&wfh, g_wfh); cudaGetSymbolAddress((void**)&wfl, g_wfl);
  cudaGetSymbolAddress((void**)&w1h, g_w1h); cudaGetSymbolAddress((void**)&w1l, g_w1l);
  cudaGetSymbolAddress((void**)&w2h, g_w2h); cudaGetSymbolAddress((void**)&w2l, g_w2l);

  static int smem_set = 0;
  if (!smem_set){
    cudaFuncSetAttribute(gemm_mma, cudaFuncAttributeMaxDynamicSharedMemorySize, 65536);
    smem_set = 1;
  }

  const int M = 8192, D = 1024;
  const int GSM = 65536;
  dim3 tb(32, 8);
  dim3 tD(D/32, D/32);

  transp_split<<<tD, tb>>>(Wq, wqh, wql, D, D);
  transp_split<<<tD, tb>>>(Wk, wkh, wkl, D, D);
  transp_split<<<tD, tb>>>(Wv, wvh, wvl, D, D);
  transp_split<<<tD, tb>>>(Wfc, wfh, wfl, D, D);
  transp_split<<<dim3(4*D/32, D/32), tb>>>(W1, w1h, w1l, D, 4*D);
  transp_split<<<dim3(D/32, 4*D/32), tb>>>(W2, w2h, w2l, 4*D, D);

  dim3 gD(D/128, M/128);       // (8, 64)
  dim3 gF(4*D/128, M/128);     // (32, 64)

  ln1024_split<<<M, 256>>>(x, g1, b1, xlh, xll);
  gemm_mma<<<gD, 256, GSM>>>(xlh, xll, wqh, wql, nullptr, nullptr, q, nullptr, nullptr,
                             M, D, D, 0, 0);
  gemm_mma<<<gD, 256, GSM>>>(xlh, xll, wkh, wkl, nullptr, nullptr, k, nullptr, nullptr,
                             M, D, D, 0, 0);
  gemm_mma<<<gD, 256, GSM>>>(xlh, xll, wvh, wvl, nullptr, nullptr, v, nullptr, nullptr,
                             M, D, D, 0, 0);
  attn64<<<dim3(32, 16, 4), 256>>>(q, k, v, oh, ol);
  gemm_mma<<<gD, 256, GSM>>>(oh, ol, wfh, wfl, bfc, x, x2, nullptr, nullptr,
                             M, D, D, 0, 0);
  ln1024_split<<<M, 256>>>(x2, g2, b2, xlh, xll);
  gemm_mma<<<gF, 256, GSM>>>(xlh, xll, w1h, w1l, bf1, nullptr, nullptr, hh, hl,
                             M, 4*D, D, 1, 1);
  gemm_mma<<<gD, 256, GSM>>>(hh, hl, w2h, w2l, bf2, x2, out, nullptr, nullptr,
                             M, D, 4*D, 0, 0);
}

// round 4
// speedup vs baseline: 2.8353x; 1.6273x over previous
#include <cuda_runtime.h>
#include <cuda_bf16.h>
#include <cstdint>

typedef unsigned long long ull;

// ---- PTX helpers (portable sm_80+) ----
__device__ __forceinline__ uint32_t s2u(const void* p){
  uint32_t a; asm("{ .reg .u64 t; cvta.to.shared.u64 t, %1; cvt.u32.u64 %0, t; }"
                  : "=r"(a) : "l"(p));
  return a;
}
__device__ __forceinline__ void ldsm4(uint32_t* r, uint32_t a){
  asm volatile("ldmatrix.sync.aligned.m8n8.x4.shared.b16 {%0,%1,%2,%3}, [%4];"
               : "=r"(r[0]), "=r"(r[1]), "=r"(r[2]), "=r"(r[3]) : "r"(a));
}
__device__ __forceinline__ void ldsm4t(uint32_t* r, uint32_t a){
  asm volatile("ldmatrix.sync.aligned.m8n8.x4.trans.shared.b16 {%0,%1,%2,%3}, [%4];"
               : "=r"(r[0]), "=r"(r[1]), "=r"(r[2]), "=r"(r[3]) : "r"(a));
}
__device__ __forceinline__ void mma16816(float* d, const uint32_t* a, const uint32_t* b){
  asm volatile(
    "mma.sync.aligned.m16n8k16.row.col.f32.bf16.bf16.f32 "
    "{%0,%1,%2,%3}, {%4,%5,%6,%7}, {%8,%9}, {%0,%1,%2,%3};"
    : "+f"(d[0]), "+f"(d[1]), "+f"(d[2]), "+f"(d[3])
    : "r"(a[0]), "r"(a[1]), "r"(a[2]), "r"(a[3]), "r"(b[0]), "r"(b[1]));
}
__device__ __forceinline__ void cpasync16(uint32_t dst, const void* src){
  asm volatile("cp.async.cg.shared.global [%0], [%1], 16;" :: "r"(dst), "l"(src) : "memory");
}
#define CP_COMMIT() asm volatile("cp.async.commit_group;" ::: "memory")
#define CP_WAIT1()  asm volatile("cp.async.wait_group 1;" ::: "memory")
#define CP_WAIT0()  asm volatile("cp.async.wait_group 0;" ::: "memory")

#define SWZ(o) ((o) ^ (((o) >> 3) & 0x70))

// ======================= scratch (device globals) =======================
#define MR 8192
#define DD 1024
__device__ __nv_bfloat16 g_xlh[MR*DD], g_xll[MR*DD];
__device__ __nv_bfloat16 g_qh[MR*DD], g_ql[MR*DD];
__device__ __nv_bfloat16 g_kh[MR*DD], g_kl[MR*DD];
__device__ __nv_bfloat16 g_vh[MR*DD], g_vl[MR*DD];
__device__ __nv_bfloat16 g_oh[MR*DD], g_ol[MR*DD];
__device__ float g_x2[MR*DD];
__device__ __nv_bfloat16 g_hh[MR*4*DD], g_hl[MR*4*DD];
__device__ __nv_bfloat16 g_wqh[DD*DD], g_wql[DD*DD];
__device__ __nv_bfloat16 g_wkh[DD*DD], g_wkl[DD*DD];
__device__ __nv_bfloat16 g_wvh[DD*DD], g_wvl[DD*DD];
__device__ __nv_bfloat16 g_wfh[DD*DD], g_wfl[DD*DD];
__device__ __nv_bfloat16 g_w1h[4*DD*DD], g_w1l[4*DD*DD];
__device__ __nv_bfloat16 g_w2h[4*DD*DD], g_w2l[4*DD*DD];

// ======================= LayerNorm -> bf16 hi/lo =======================
__global__ __launch_bounds__(256) void ln1024_split(
    const float* __restrict__ x, const float* __restrict__ g,
    const float* __restrict__ bt, __nv_bfloat16* __restrict__ yh,
    __nv_bfloat16* __restrict__ yl)
{
  int row = blockIdx.x;
  const float4* xr = (const float4*)(x + (size_t)row * 1024);
  float4 v = xr[threadIdx.x];
  float s = v.x + v.y + v.z + v.w;
  float q = v.x*v.x + v.y*v.y + v.z*v.z + v.w*v.w;
  #pragma unroll
  for (int off = 16; off; off >>= 1){
    s += __shfl_xor_sync(0xffffffffu, s, off);
    q += __shfl_xor_sync(0xffffffffu, q, off);
  }
  __shared__ float ss[8], qs[8];
  int w = threadIdx.x >> 5;
  if ((threadIdx.x & 31) == 0){ ss[w] = s; qs[w] = q; }
  __syncthreads();
  s = ss[0]+ss[1]+ss[2]+ss[3]+ss[4]+ss[5]+ss[6]+ss[7];
  q = qs[0]+qs[1]+qs[2]+qs[3]+qs[4]+qs[5]+qs[6]+qs[7];
  float mu   = s * (1.0f/1024.0f);
  float var  = q * (1.0f/1024.0f) - mu*mu;
  float rstd = rsqrtf(var + 1e-5f);
  int c = threadIdx.x * 4;
  float4 gg = *(const float4*)(g  + c);
  float4 bb = *(const float4*)(bt + c);
  float o0 = (v.x-mu)*rstd*gg.x + bb.x;
  float o1 = (v.y-mu)*rstd*gg.y + bb.y;
  float o2 = (v.z-mu)*rstd*gg.z + bb.z;
  float o3 = (v.w-mu)*rstd*gg.w + bb.w;
  __nv_bfloat16 h0=__float2bfloat16(o0), h1=__float2bfloat16(o1);
  __nv_bfloat16 h2=__float2bfloat16(o2), h3=__float2bfloat16(o3);
  __nv_bfloat162 ph0; ph0.x=h0; ph0.y=h1;
  __nv_bfloat162 ph1; ph1.x=h2; ph1.y=h3;
  __nv_bfloat162 pl0; pl0.x=__float2bfloat16(o0-__bfloat162float(h0));
                      pl0.y=__float2bfloat16(o1-__bfloat162float(h1));
  __nv_bfloat162 pl1; pl1.x=__float2bfloat16(o2-__bfloat162float(h2));
                      pl1.y=__float2bfloat16(o3-__bfloat162float(h3));
  size_t idx = (size_t)row*1024 + c;
  *(__nv_bfloat162*)(yh+idx)   = ph0; *(__nv_bfloat162*)(yh+idx+2) = ph1;
  *(__nv_bfloat162*)(yl+idx)   = pl0; *(__nv_bfloat162*)(yl+idx+2) = pl1;
}

// ======================= weight transpose + split =======================
__global__ void transp_split(const float* __restrict__ W,
                             __nv_bfloat16* __restrict__ Th,
                             __nv_bfloat16* __restrict__ Tl, int K, int N)
{
  __shared__ float t[32][33];
  int n0 = blockIdx.x*32, k0 = blockIdx.y*32;
  int tx = threadIdx.x, ty = threadIdx.y; // 32 x 8
  #pragma unroll
  for (int j = 0; j < 4; j++)
    t[ty+8*j][tx] = W[(size_t)(k0+ty+8*j)*N + n0+tx];
  __syncthreads();
  #pragma unroll
  for (int j = 0; j < 4; j++){
    float v = t[tx][ty+8*j];
    __nv_bfloat16 h = __float2bfloat16(v);
    size_t idx = (size_t)(n0+ty+8*j)*K + k0+tx;
    Th[idx] = h;
    Tl[idx] = __float2bfloat16(v - __bfloat162float(h));
  }
}

// ======================= split-bf16 GEMM (HMMA, 3-stage cp.async) =======================
__global__ __launch_bounds__(256) void gemm_mma(
    const __nv_bfloat16* __restrict__ Ahi, const __nv_bfloat16* __restrict__ Alo,
    const __nv_bfloat16* __restrict__ Bhi, const __nv_bfloat16* __restrict__ Blo,
    const float* __restrict__ bias, const float* __restrict__ res,
    float* __restrict__ C, __nv_bfloat16* __restrict__ Chi,
    __nv_bfloat16* __restrict__ Clo,
    int M, int N, int K, int relu, int split)
{
  extern __shared__ __align__(1024) char smem[];
  const int tid = threadIdx.x, lane = tid & 31, wid = tid >> 5;
  const int m0 = blockIdx.y * 128, n0 = blockIdx.x * 128;
  const int wm = (wid >> 1) * 32, wn = (wid & 1) * 64;
  const uint32_t aS0 = s2u(smem);

  const int nck = K >> 6;
  const int nc  = 3 * nck;

  float acc[2][8][4];
  #pragma unroll
  for (int i = 0; i < 2; i++)
    #pragma unroll
    for (int j = 0; j < 8; j++)
      #pragma unroll
      for (int r = 0; r < 4; r++) acc[i][j][r] = 0.f;

  const int rowA = lane & 15;
  const int kbA  = (lane & 16) ? 16 : 0;
  const int rowB = (lane & 7) + ((lane & 16) ? 8 : 0);
  const int kbB  = (lane & 8) ? 16 : 0;

  uint32_t swoff[4]; int ldr[4], ldc[4];
  #pragma unroll
  for (int i = 0; i < 4; i++){
    int gg = tid + 256*i;
    ldr[i] = gg >> 3; ldc[i] = (gg & 7) * 8;
    swoff[i] = SWZ((uint32_t)(ldr[i]*128 + (gg & 7)*16));
  }

  #define ISSUE(c) do { \
    int _p = (c) / nck, _kk = (c) - _p * nck, _k0 = _kk << 6; \
    const __nv_bfloat16* _Ap = (_p == 2) ? Alo : Ahi; \
    const __nv_bfloat16* _Bp = (_p == 1) ? Blo : Bhi; \
    uint32_t _dA = aS0 + ((c) % 3) * 32768; \
    uint32_t _dB = _dA + 16384; \
    _Pragma("unroll") \
    for (int _i = 0; _i < 4; _i++){ \
      cpasync16(_dA + swoff[_i], _Ap + (size_t)(m0 + ldr[_i]) * K + _k0 + ldc[_i]); \
      cpasync16(_dB + swoff[_i], _Bp + (size_t)(n0 + ldr[_i]) * K + _k0 + ldc[_i]); \
    } \
    CP_COMMIT(); \
  } while(0)

  ISSUE(0); ISSUE(1);
  for (int c = 0; c < nc; c++){
    if (c + 1 < nc){ CP_WAIT1(); } else { CP_WAIT0(); }
    __syncthreads();
    if (c + 2 < nc) ISSUE(c + 2);
    const uint32_t bA = aS0 + (c % 3) * 32768;
    const uint32_t bB = bA + 16384;
    #pragma unroll
    for (int s = 0; s < 4; s++){
      uint32_t af[2][4];
      #pragma unroll
      for (int mi = 0; mi < 2; mi++){
        uint32_t off = (uint32_t)((wm + mi*16 + rowA)*128 + s*32 + kbA);
        ldsm4(af[mi], bA + SWZ(off));
      }
      uint32_t bfr[4][4];
      #pragma unroll
      for (int njp = 0; njp < 4; njp++){
        uint32_t off = (uint32_t)((wn + njp*16 + rowB)*128 + s*32 + kbB);
        ldsm4(bfr[njp], bB + SWZ(off));
      }
      #pragma unroll
      for (int mi = 0; mi < 2; mi++)
        #pragma unroll
        for (int nj = 0; nj < 8; nj++)
          mma16816(acc[mi][nj], af[mi], &bfr[nj >> 1][(nj & 1) * 2]);
    }
  }
  #undef ISSUE

  const int er = lane >> 2, ec = (lane & 3) * 2;
  #pragma unroll
  for (int mi = 0; mi < 2; mi++){
    #pragma unroll
    for (int half = 0; half < 2; half++){
      int row = m0 + wm + mi*16 + er + half*8;
      #pragma unroll
      for (int nj = 0; nj < 8; nj++){
        int col = n0 + wn + nj*8 + ec;
        float v0 = acc[mi][nj][half*2 + 0];
        float v1 = acc[mi][nj][half*2 + 1];
        if (bias){
          float2 bv = *(const float2*)(bias + col);
          v0 += bv.x; v1 += bv.y;
        }
        if (relu){ v0 = fmaxf(v0, 0.f); v1 = fmaxf(v1, 0.f); }
        if (res){
          float2 rv = *(const float2*)(res + (size_t)row*N + col);
          v0 += rv.x; v1 += rv.y;
        }
        size_t idx = (size_t)row*N + col;
        if (split){
          __nv_bfloat16 h0 = __float2bfloat16(v0), h1 = __float2bfloat16(v1);
          __nv_bfloat162 ph; ph.x = h0; ph.y = h1;
          __nv_bfloat162 pl;
          pl.x = __float2bfloat16(v0 - __bfloat162float(h0));
          pl.y = __float2bfloat16(v1 - __bfloat162float(h1));
          *(__nv_bfloat162*)(Chi + idx) = ph;
          *(__nv_bfloat162*)(Clo + idx) = pl;
        } else {
          float2 o; o.x = v0; o.y = v1;
          *(float2*)(C + idx) = o;
        }
      }
    }
  }
}

// ======================= flash attention via HMMA, split-bf16 =======================
// Q tile 128 rows per CTA; KV tiles of 64, double-buffered cp.async.
// smem: [0,16K) Qhi, [16K,32K) Qlo, stage s at 32K+s*32K: {Khi 8K,Klo 8K,Vhi 8K,Vlo 8K}
__global__ __launch_bounds__(256, 1) void attn_mma(
    const __nv_bfloat16* __restrict__ Qh, const __nv_bfloat16* __restrict__ Ql,
    const __nv_bfloat16* __restrict__ Kh, const __nv_bfloat16* __restrict__ Kl,
    const __nv_bfloat16* __restrict__ Vh, const __nv_bfloat16* __restrict__ Vl,
    __nv_bfloat16* __restrict__ Oh, __nv_bfloat16* __restrict__ Ol)
{
  extern __shared__ __align__(1024) char smem[];
  const int tid = threadIdx.x, lane = tid & 31, warp = tid >> 5;
  const int b = blockIdx.z, h = blockIdx.y, q0 = blockIdx.x * 128;
  const size_t base = ((size_t)b * 2048) * 1024 + h * 64;
  const uint32_t aQ = s2u(smem);
  const uint32_t aKV = aQ + 32768;
  const int wm = warp * 16;

  const int rowA = lane & 15;
  const int kbA  = (lane & 16) ? 16 : 0;
  const int rowB = (lane & 7) + ((lane & 16) ? 8 : 0);
  const int kbB  = (lane & 8) ? 16 : 0;
  const int kvr  = lane & 15;
  const int ncb  = (lane & 16) ? 8 : 0;

  // ---- preload Q (group 0) ----
  #pragma unroll
  for (int i = 0; i < 4; i++){
    int gg = tid + 256*i;
    int r = gg >> 3, c = gg & 7;
    uint32_t d = SWZ((uint32_t)(r*128 + c*16));
    const size_t src = base + (size_t)(q0 + r) * 1024 + c*8;
    cpasync16(aQ + d, Qh + src);
    cpasync16(aQ + 16384 + d, Ql + src);
  }
  CP_COMMIT();

  #define ISSUEKV(j) do { \
    uint32_t _st = aKV + ((j) & 1) * 32768; \
    int _j0 = (j) * 64; \
    _Pragma("unroll") \
    for (int _i = 0; _i < 2; _i++){ \
      int _gg = tid + 256*_i; \
      int _r = _gg >> 3, _c = _gg & 7; \
      uint32_t _d = SWZ((uint32_t)(_r*128 + _c*16)); \
      const size_t _src = base + (size_t)(_j0 + _r) * 1024 + _c*8; \
      cpasync16(_st + _d,         Kh + _src); \
      cpasync16(_st + 8192 + _d,  Kl + _src); \
      cpasync16(_st + 16384 + _d, Vh + _src); \
      cpasync16(_st + 24576 + _d, Vl + _src); \
    } \
    CP_COMMIT(); \
  } while(0)

  ISSUEKV(0);
  CP_WAIT1();          // Q arrived (kv0 may pend)
  __syncthreads();

  // ---- Q fragments (persist in registers) ----
  uint32_t qfh[4][4], qfl[4][4];
  #pragma unroll
  for (int s = 0; s < 4; s++){
    uint32_t off = SWZ((uint32_t)((wm + rowA)*128 + s*32 + kbA));
    ldsm4(qfh[s], aQ + off);
    ldsm4(qfl[s], aQ + 16384 + off);
  }

  float m0 = -1e30f, m1 = -1e30f, l0 = 0.f, l1 = 0.f;
  float oa[8][4];
  #pragma unroll
  for (int nb = 0; nb < 8; nb++)
    #pragma unroll
    for (int r = 0; r < 4; r++) oa[nb][r] = 0.f;

  #pragma unroll 1
  for (int jt = 0; jt < 32; jt++){
    if (jt + 1 < 32){ ISSUEKV(jt + 1); CP_WAIT1(); }
    else            { CP_WAIT0(); }
    __syncthreads();
    const uint32_t st = aKV + (jt & 1) * 32768;

    // ---- S = (Qhi+Qlo)(Khi)^T + Qhi(Klo)^T ----
    float sc[8][4];
    #pragma unroll
    for (int nb = 0; nb < 8; nb++)
      #pragma unroll
      for (int r = 0; r < 4; r++) sc[nb][r] = 0.f;
    #pragma unroll
    for (int s = 0; s < 4; s++){
      #pragma unroll
      for (int g = 0; g < 4; g++){
        uint32_t off = SWZ((uint32_t)((g*16 + rowB)*128 + s*32 + kbB));
        uint32_t kh4[4], kl4[4];
        ldsm4(kh4, st + off);
        ldsm4(kl4, st + 8192 + off);
        mma16816(sc[2*g],   qfh[s], kh4);
        mma16816(sc[2*g+1], qfh[s], kh4 + 2);
        mma16816(sc[2*g],   qfl[s], kh4);
        mma16816(sc[2*g+1], qfl[s], kh4 + 2);
        mma16816(sc[2*g],   qfh[s], kl4);
        mma16816(sc[2*g+1], qfh[s], kl4 + 2);
      }
    }

    // ---- online softmax (scores *= 8 per reference quirk) ----
    float mx0 = -1e30f, mx1 = -1e30f;
    #pragma unroll
    for (int nb = 0; nb < 8; nb++){
      sc[nb][0] *= 8.f; sc[nb][1] *= 8.f; sc[nb][2] *= 8.f; sc[nb][3] *= 8.f;
      mx0 = fmaxf(mx0, fmaxf(sc[nb][0], sc[nb][1]));
      mx1 = fmaxf(mx1, fmaxf(sc[nb][2], sc[nb][3]));
    }
    mx0 = fmaxf(mx0, __shfl_xor_sync(0xffffffffu, mx0, 1));
    mx0 = fmaxf(mx0, __shfl_xor_sync(0xffffffffu, mx0, 2));
    mx1 = fmaxf(mx1, __shfl_xor_sync(0xffffffffu, mx1, 1));
    mx1 = fmaxf(mx1, __shfl_xor_sync(0xffffffffu, mx1, 2));
    float nm0 = fmaxf(m0, mx0), nm1 = fmaxf(m1, mx1);
    float a0 = __expf(m0 - nm0), a1 = __expf(m1 - nm1);
    m0 = nm0; m1 = nm1;

    float rs0 = 0.f, rs1 = 0.f;
    uint32_t pfh[4][4], pfl[4][4];
    #pragma unroll
    for (int nb = 0; nb < 8; nb++){
      float p00 = __expf(sc[nb][0] - nm0), p01 = __expf(sc[nb][1] - nm0);
      float p10 = __expf(sc[nb][2] - nm1), p11 = __expf(sc[nb][3] - nm1);
      rs0 += p00 + p01; rs1 += p10 + p11;
      __nv_bfloat162 h0 = __floats2bfloat162_rn(p00, p01);
      __nv_bfloat162 h1 = __floats2bfloat162_rn(p10, p11);
      __nv_bfloat162 lo0 = __floats2bfloat162_rn(p00 - __bfloat162float(h0.x),
                                                 p01 - __bfloat162float(h0.y));
      __nv_bfloat162 lo1 = __floats2bfloat162_rn(p10 - __bfloat162float(h1.x),
                                                 p11 - __bfloat162float(h1.y));
      int j = nb >> 1, rq = (nb & 1) * 2;
      pfh[j][rq]   = *(uint32_t*)&h0;  pfh[j][rq+1] = *(uint32_t*)&h1;
      pfl[j][rq]   = *(uint32_t*)&lo0; pfl[j][rq+1] = *(uint32_t*)&lo1;
    }
    rs0 += __shfl_xor_sync(0xffffffffu, rs0, 1);
    rs0 += __shfl_xor_sync(0xffffffffu, rs0, 2);
    rs1 += __shfl_xor_sync(0xffffffffu, rs1, 1);
    rs1 += __shfl_xor_sync(0xffffffffu, rs1, 2);
    l0 = l0 * a0 + rs0; l1 = l1 * a1 + rs1;
    #pragma unroll
    for (int nb = 0; nb < 8; nb++){
      oa[nb][0] *= a0; oa[nb][1] *= a0; oa[nb][2] *= a1; oa[nb][3] *= a1;
    }

    // ---- O += (Phi+Plo) Vhi + Phi Vlo ----
    #pragma unroll
    for (int s = 0; s < 4; s++){
      #pragma unroll
      for (int g = 0; g < 4; g++){
        uint32_t off = SWZ((uint32_t)((s*16 + kvr)*128 + (g*16 + ncb)*2));
        uint32_t vh4[4], vl4[4];
        ldsm4t(vh4, st + 16384 + off);
        ldsm4t(vl4, st + 24576 + off);
        mma16816(oa[2*g],   pfh[s], vh4);
        mma16816(oa[2*g+1], pfh[s], vh4 + 2);
        mma16816(oa[2*g],   pfl[s], vh4);
        mma16816(oa[2*g+1], pfl[s], vh4 + 2);
        mma16816(oa[2*g],   pfh[s], vl4);
        mma16816(oa[2*g+1], pfh[s], vl4 + 2);
      }
    }
    __syncthreads();
  }

  // ---- epilogue: normalize, split, store ----
  const int er = lane >> 2, ec = (lane & 3) * 2;
  float i0 = 1.0f / l0, i1 = 1.0f / l1;
  const int r0 = q0 + wm + er;
  #pragma unroll
  for (int nb = 0; nb < 8; nb++){
    int col = nb*8 + ec;
    float v0 = oa[nb][0]*i0, v1 = oa[nb][1]*i0;
    float v2 = oa[nb][2]*i1, v3 = oa[nb][3]*i1;
    __nv_bfloat162 h0 = __floats2bfloat162_rn(v0, v1);
    __nv_bfloat162 h1 = __floats2bfloat162_rn(v2, v3);
    __nv_bfloat162 lo0 = __floats2bfloat162_rn(v0 - __bfloat162float(h0.x),
                                               v1 - __bfloat162float(h0.y));
    __nv_bfloat162 lo1 = __floats2bfloat162_rn(v2 - __bfloat162float(h1.x),
                                               v3 - __bfloat162float(h1.y));
    size_t i0x = base + (size_t)r0 * 1024 + col;
    size_t i1x = base + (size_t)(r0 + 8) * 1024 + col;
    *(__nv_bfloat162*)(Oh + i0x) = h0;
    *(__nv_bfloat162*)(Ol + i0x) = lo0;
    *(__nv_bfloat162*)(Oh + i1x) = h1;
    *(__nv_bfloat162*)(Ol + i1x) = lo1;
  }
  #undef ISSUEKV
}

// ======================= launch =======================
extern "C" void kernel_launch(void* const* d_in, const int* in_sizes, int n_in,
                              void* d_out, int out_size)
{
  (void)in_sizes; (void)n_in; (void)out_size;
  const float* x   = (const float*)d_in[0];
  const float* Wk  = (const float*)d_in[2];
  const float* Wq  = (const float*)d_in[3];
  const float* Wv  = (const float*)d_in[4];
  const float* Wfc = (const float*)d_in[5];
  const float* bfc = (const float*)d_in[6];
  const float* g1  = (const float*)d_in[7];
  const float* b1  = (const float*)d_in[8];
  const float* g2  = (const float*)d_in[9];
  const float* b2  = (const float*)d_in[10];
  const float* W1  = (const float*)d_in[11];
  const float* bf1 = (const float*)d_in[12];
  const float* W2  = (const float*)d_in[13];
  const float* bf2 = (const float*)d_in[14];
  float* out = (float*)d_out;

  __nv_bfloat16 *xlh,*xll,*qh,*ql,*kh,*kl,*vh,*vl,*oh,*ol,*hh,*hl;
  __nv_bfloat16 *wqh,*wql,*wkh,*wkl,*wvh,*wvl,*wfh,*wfl,*w1h,*w1l,*w2h,*w2l;
  float *x2;
  cudaGetSymbolAddress((void**)&xlh, g_xlh); cudaGetSymbolAddress((void**)&xll, g_xll);
  cudaGetSymbolAddress((void**)&qh, g_qh); cudaGetSymbolAddress((void**)&ql, g_ql);
  cudaGetSymbolAddress((void**)&kh, g_kh); cudaGetSymbolAddress((void**)&kl, g_kl);
  cudaGetSymbolAddress((void**)&vh, g_vh); cudaGetSymbolAddress((void**)&vl, g_vl);
  cudaGetSymbolAddress((void**)&oh, g_oh); cudaGetSymbolAddress((void**)&ol, g_ol);
  cudaGetSymbolAddress((void**)&x2, g_x2);
  cudaGetSymbolAddress((void**)&hh, g_hh); cudaGetSymbolAddress((void**)&hl, g_hl);
  cudaGetSymbolAddress((void**)&wqh, g_wqh); cudaGetSymbolAddress((void**)&wql, g_wql);
  cudaGetSymbolAddress((void**)&wkh, g_wkh); cudaGetSymbolAddress((void**)&wkl, g_wkl);
  cudaGetSymbolAddress((void**)&wvh, g_wvh); cudaGetSymbolAddress((void**)&wvl, g_wvl);
  cudaGetSymbolAddress((void**)&wfh, g_wfh); cudaGetSymbolAddress((void**)&wfl, g_wfl);
  cudaGetSymbolAddress((void**)&w1h, g_w1h); cudaGetSymbolAddress((void**)&w1l, g_w1l);
  cudaGetSymbolAddress((void**)&w2h, g_w2h); cudaGetSymbolAddress((void**)&w2l, g_w2l);

  static int smem_set = 0;
  if (!smem_set){
    cudaFuncSetAttribute(gemm_mma, cudaFuncAttributeMaxDynamicSharedMemorySize, 98304);
    cudaFuncSetAttribute(attn_mma, cudaFuncAttributeMaxDynamicSharedMemorySize, 98304);
    smem_set = 1;
  }

  const int M = 8192, D = 1024;
  const int GSM = 98304;
  dim3 tb(32, 8);
  dim3 tD(D/32, D/32);

  transp_split<<<tD, tb>>>(Wq, wqh, wql, D, D);
  transp_split<<<tD, tb>>>(Wk, wkh, wkl, D, D);
  transp_split<<<tD, tb>>>(Wv, wvh, wvl, D, D);
  transp_split<<<tD, tb>>>(Wfc, wfh, wfl, D, D);
  transp_split<<<dim3(4*D/32, D/32), tb>>>(W1, w1h, w1l, D, 4*D);
  transp_split<<<dim3(D/32, 4*D/32), tb>>>(W2, w2h, w2l, 4*D, D);

  dim3 gD(D/128, M/128);       // (8, 64)
  dim3 gF(4*D/128, M/128);     // (32, 64)

  ln1024_split<<<M, 256>>>(x, g1, b1, xlh, xll);
  gemm_mma<<<gD, 256, GSM>>>(xlh, xll, wqh, wql, nullptr, nullptr, nullptr, qh, ql,
                             M, D, D, 0, 1);
  gemm_mma<<<gD, 256, GSM>>>(xlh, xll, wkh, wkl, nullptr, nullptr, nullptr, kh, kl,
                             M, D, D, 0, 1);
  gemm_mma<<<gD, 256, GSM>>>(xlh, xll, wvh, wvl, nullptr, nullptr, nullptr, vh, vl,
                             M, D, D, 0, 1);
  attn_mma<<<dim3(16, 16, 4), 256, GSM>>>(qh, ql, kh, kl, vh, vl, oh, ol);
  gemm_mma<<<gD, 256, GSM>>>(oh, ol, wfh, wfl, bfc, x, x2, nullptr, nullptr,
                             M, D, D, 0, 0);
  ln1024_split<<<M, 256>>>(x2, g2, b2, xlh, xll);
  gemm_mma<<<gF, 256, GSM>>>(xlh, xll, w1h, w1l, bf1, nullptr, nullptr, hh, hl,
                             M, 4*D, D, 1, 1);
  gemm_mma<<<gD, 256, GSM>>>(hh, hl, w2h, w2l, bf2, x2, out, nullptr, nullptr,
                             M, D, 4*D, 0, 0);
}

// round 6
// speedup vs baseline: 3.3017x; 1.1645x over previous
#include <cuda_runtime.h>
#include <cuda_bf16.h>
#include <cstdint>

typedef unsigned long long ull;

// ---- PTX helpers (portable sm_80+) ----
__device__ __forceinline__ uint32_t s2u(const void* p){
  uint32_t a; asm("{ .reg .u64 t; cvta.to.shared.u64 t, %1; cvt.u32.u64 %0, t; }"
                  : "=r"(a) : "l"(p));
  return a;
}
__device__ __forceinline__ void ldsm4(uint32_t* r, uint32_t a){
  asm volatile("ldmatrix.sync.aligned.m8n8.x4.shared.b16 {%0,%1,%2,%3}, [%4];"
               : "=r"(r[0]), "=r"(r[1]), "=r"(r[2]), "=r"(r[3]) : "r"(a));
}
__device__ __forceinline__ void ldsm4t(uint32_t* r, uint32_t a){
  asm volatile("ldmatrix.sync.aligned.m8n8.x4.trans.shared.b16 {%0,%1,%2,%3}, [%4];"
               : "=r"(r[0]), "=r"(r[1]), "=r"(r[2]), "=r"(r[3]) : "r"(a));
}
__device__ __forceinline__ void mma16816(float* d, const uint32_t* a, const uint32_t* b){
  asm volatile(
    "mma.sync.aligned.m16n8k16.row.col.f32.bf16.bf16.f32 "
    "{%0,%1,%2,%3}, {%4,%5,%6,%7}, {%8,%9}, {%0,%1,%2,%3};"
    : "+f"(d[0]), "+f"(d[1]), "+f"(d[2]), "+f"(d[3])
    : "r"(a[0]), "r"(a[1]), "r"(a[2]), "r"(a[3]), "r"(b[0]), "r"(b[1]));
}
__device__ __forceinline__ void cpasync16(uint32_t dst, const void* src){
  asm volatile("cp.async.cg.shared.global [%0], [%1], 16;" :: "r"(dst), "l"(src) : "memory");
}
#define CP_COMMIT() asm volatile("cp.async.commit_group;" ::: "memory")
#define CP_WAIT1()  asm volatile("cp.async.wait_group 1;" ::: "memory")
#define CP_WAIT0()  asm volatile("cp.async.wait_group 0;" ::: "memory")

#define SWZ(o) ((o) ^ (((o) >> 3) & 0x70))

// ======================= scratch (device globals) =======================
#define MR 8192
#define DD 1024
__device__ __nv_bfloat16 g_xlh[MR*DD], g_xll[MR*DD];
__device__ __nv_bfloat16 g_qkvh[MR*3*DD], g_qkvl[MR*3*DD];
__device__ __nv_bfloat16 g_oh[MR*DD], g_ol[MR*DD];
__device__ float g_x2[MR*DD];
__device__ __nv_bfloat16 g_hh[MR*4*DD], g_hl[MR*4*DD];
__device__ __nv_bfloat16 g_wqkvh[3*DD*DD], g_wqkvl[3*DD*DD];
__device__ __nv_bfloat16 g_wfh[DD*DD], g_wfl[DD*DD];
__device__ __nv_bfloat16 g_w1h[4*DD*DD], g_w1l[4*DD*DD];
__device__ __nv_bfloat16 g_w2h[4*DD*DD], g_w2l[4*DD*DD];

// ======================= LayerNorm -> bf16 hi/lo =======================
__global__ __launch_bounds__(256) void ln1024_split(
    const float* __restrict__ x, const float* __restrict__ g,
    const float* __restrict__ bt, __nv_bfloat16* __restrict__ yh,
    __nv_bfloat16* __restrict__ yl)
{
  int row = blockIdx.x;
  const float4* xr = (const float4*)(x + (size_t)row * 1024);
  float4 v = xr[threadIdx.x];
  float s = v.x + v.y + v.z + v.w;
  float q = v.x*v.x + v.y*v.y + v.z*v.z + v.w*v.w;
  #pragma unroll
  for (int off = 16; off; off >>= 1){
    s += __shfl_xor_sync(0xffffffffu, s, off);
    q += __shfl_xor_sync(0xffffffffu, q, off);
  }
  __shared__ float ss[8], qs[8];
  int w = threadIdx.x >> 5;
  if ((threadIdx.x & 31) == 0){ ss[w] = s; qs[w] = q; }
  __syncthreads();
  s = ss[0]+ss[1]+ss[2]+ss[3]+ss[4]+ss[5]+ss[6]+ss[7];
  q = qs[0]+qs[1]+qs[2]+qs[3]+qs[4]+qs[5]+qs[6]+qs[7];
  float mu   = s * (1.0f/1024.0f);
  float var  = q * (1.0f/1024.0f) - mu*mu;
  float rstd = rsqrtf(var + 1e-5f);
  int c = threadIdx.x * 4;
  float4 gg = *(const float4*)(g  + c);
  float4 bb = *(const float4*)(bt + c);
  float o0 = (v.x-mu)*rstd*gg.x + bb.x;
  float o1 = (v.y-mu)*rstd*gg.y + bb.y;
  float o2 = (v.z-mu)*rstd*gg.z + bb.z;
  float o3 = (v.w-mu)*rstd*gg.w + bb.w;
  __nv_bfloat16 h0=__float2bfloat16(o0), h1=__float2bfloat16(o1);
  __nv_bfloat16 h2=__float2bfloat16(o2), h3=__float2bfloat16(o3);
  __nv_bfloat162 ph0; ph0.x=h0; ph0.y=h1;
  __nv_bfloat162 ph1; ph1.x=h2; ph1.y=h3;
  __nv_bfloat162 pl0; pl0.x=__float2bfloat16(o0-__bfloat162float(h0));
                      pl0.y=__float2bfloat16(o1-__bfloat162float(h1));
  __nv_bfloat162 pl1; pl1.x=__float2bfloat16(o2-__bfloat162float(h2));
                      pl1.y=__float2bfloat16(o3-__bfloat162float(h3));
  size_t idx = (size_t)row*1024 + c;
  *(__nv_bfloat162*)(yh+idx)   = ph0; *(__nv_bfloat162*)(yh+idx+2) = ph1;
  *(__nv_bfloat162*)(yl+idx)   = pl0; *(__nv_bfloat162*)(yl+idx+2) = pl1;
}

// ======================= weight transpose + split =======================
__global__ void transp_split(const float* __restrict__ W,
                             __nv_bfloat16* __restrict__ Th,
                             __nv_bfloat16* __restrict__ Tl, int K, int N)
{
  __shared__ float t[32][33];
  int n0 = blockIdx.x*32, k0 = blockIdx.y*32;
  int tx = threadIdx.x, ty = threadIdx.y; // 32 x 8
  #pragma unroll
  for (int j = 0; j < 4; j++)
    t[ty+8*j][tx] = W[(size_t)(k0+ty+8*j)*N + n0+tx];
  __syncthreads();
  #pragma unroll
  for (int j = 0; j < 4; j++){
    float v = t[tx][ty+8*j];
    __nv_bfloat16 h = __float2bfloat16(v);
    size_t idx = (size_t)(n0+ty+8*j)*K + k0+tx;
    Th[idx] = h;
    Tl[idx] = __float2bfloat16(v - __bfloat162float(h));
  }
}

// ======================= split-bf16 GEMM (HMMA, 128x256 tile, 3-stage) =======================
// 8 warps, each 64x64 warp tile. 3-stage cp.async pipeline (144KB smem),
// issue-ahead-2 ordering (waited group always fully landed). 3 passes: hh, hi*lo, lo*hi.
__global__ __launch_bounds__(256, 1) void gemm_mma(
    const __nv_bfloat16* __restrict__ Ahi, const __nv_bfloat16* __restrict__ Alo,
    const __nv_bfloat16* __restrict__ Bhi, const __nv_bfloat16* __restrict__ Blo,
    const float* __restrict__ bias, const float* __restrict__ res,
    float* __restrict__ C, __nv_bfloat16* __restrict__ Chi,
    __nv_bfloat16* __restrict__ Clo,
    int M, int N, int K, int relu, int split)
{
  extern __shared__ __align__(1024) char smem[];
  const int tid = threadIdx.x, lane = tid & 31, wid = tid >> 5;
  const int m0 = blockIdx.y * 128, n0 = blockIdx.x * 256;
  const int wm = (wid >> 2) * 64, wn = (wid & 3) * 64;
  const uint32_t aS0 = s2u(smem);    // stage: [A 16KB][B 32KB] = 48KB; 3 stages

  const int nck = K >> 6;
  const int nc  = 3 * nck;

  float acc[4][8][4];
  #pragma unroll
  for (int i = 0; i < 4; i++)
    #pragma unroll
    for (int j = 0; j < 8; j++)
      #pragma unroll
      for (int r = 0; r < 4; r++) acc[i][j][r] = 0.f;

  const int rowA = lane & 15;
  const int kbA  = (lane & 16) ? 16 : 0;
  const int rowB = (lane & 7) + ((lane & 16) ? 8 : 0);
  const int kbB  = (lane & 8) ? 16 : 0;

  // cp.async mappings: A 4 x 16B/thread, B 8 x 16B/thread
  #define ISSUE(c) do { \
    int _p = (c) / nck, _kk = (c) - _p * nck, _k0 = _kk << 6; \
    const __nv_bfloat16* _Ap = (_p == 2) ? Alo : Ahi; \
    const __nv_bfloat16* _Bp = (_p == 1) ? Blo : Bhi; \
    uint32_t _dA = aS0 + ((c) % 3) * 49152; \
    uint32_t _dB = _dA + 16384; \
    _Pragma("unroll") \
    for (int _i = 0; _i < 4; _i++){ \
      int _gg = tid + 256*_i; int _r = _gg >> 3, _c = _gg & 7; \
      cpasync16(_dA + SWZ((uint32_t)(_r*128 + _c*16)), \
                _Ap + (size_t)(m0 + _r) * K + _k0 + _c*8); \
    } \
    _Pragma("unroll") \
    for (int _i = 0; _i < 8; _i++){ \
      int _gg = tid + 256*_i; int _r = _gg >> 3, _c = _gg & 7; \
      cpasync16(_dB + SWZ((uint32_t)(_r*128 + _c*16)), \
                _Bp + (size_t)(n0 + _r) * K + _k0 + _c*8); \
    } \
    CP_COMMIT(); \
  } while(0)

  ISSUE(0); ISSUE(1);
  for (int c = 0; c < nc; c++){
    if (c + 1 < nc){ CP_WAIT1(); } else { CP_WAIT0(); }
    __syncthreads();
    if (c + 2 < nc) ISSUE(c + 2);
    const uint32_t bA = aS0 + (c % 3) * 49152;
    const uint32_t bB = bA + 16384;
    #pragma unroll
    for (int s = 0; s < 4; s++){
      uint32_t af[4][4];
      #pragma unroll
      for (int mi = 0; mi < 4; mi++){
        uint32_t off = (uint32_t)((wm + mi*16 + rowA)*128 + s*32 + kbA);
        ldsm4(af[mi], bA + SWZ(off));
      }
      uint32_t bfr[4][4];
      #pragma unroll
      for (int njp = 0; njp < 4; njp++){
        uint32_t off = (uint32_t)((wn + njp*16 + rowB)*128 + s*32 + kbB);
        ldsm4(bfr[njp], bB + SWZ(off));
      }
      #pragma unroll
      for (int mi = 0; mi < 4; mi++)
        #pragma unroll
        for (int nj = 0; nj < 8; nj++)
          mma16816(acc[mi][nj], af[mi], &bfr[nj >> 1][(nj & 1) * 2]);
    }
  }
  #undef ISSUE

  const int er = lane >> 2, ec = (lane & 3) * 2;
  #pragma unroll
  for (int mi = 0; mi < 4; mi++){
    #pragma unroll
    for (int half = 0; half < 2; half++){
      int row = m0 + wm + mi*16 + er + half*8;
      #pragma unroll
      for (int nj = 0; nj < 8; nj++){
        int col = n0 + wn + nj*8 + ec;
        float v0 = acc[mi][nj][half*2 + 0];
        float v1 = acc[mi][nj][half*2 + 1];
        if (bias){
          float2 bv = *(const float2*)(bias + col);
          v0 += bv.x; v1 += bv.y;
        }
        if (relu){ v0 = fmaxf(v0, 0.f); v1 = fmaxf(v1, 0.f); }
        if (res){
          float2 rv = *(const float2*)(res + (size_t)row*N + col);
          v0 += rv.x; v1 += rv.y;
        }
        size_t idx = (size_t)row*N + col;
        if (split){
          __nv_bfloat16 h0 = __float2bfloat16(v0), h1 = __float2bfloat16(v1);
          __nv_bfloat162 ph; ph.x = h0; ph.y = h1;
          __nv_bfloat162 pl;
          pl.x = __float2bfloat16(v0 - __bfloat162float(h0));
          pl.y = __float2bfloat16(v1 - __bfloat162float(h1));
          *(__nv_bfloat162*)(Chi + idx) = ph;
          *(__nv_bfloat162*)(Clo + idx) = pl;
        } else {
          float2 o; o.x = v0; o.y = v1;
          *(float2*)(C + idx) = o;
        }
      }
    }
  }
}

// ======================= flash attention via HMMA, split-bf16 =======================
// QKV fused buffer [rows, 3072]: Q at col 0, K at 1024, V at 2048 (head h -> +h*64).
__global__ __launch_bounds__(256, 1) void attn_mma(
    const __nv_bfloat16* __restrict__ QKVh, const __nv_bfloat16* __restrict__ QKVl,
    __nv_bfloat16* __restrict__ Oh, __nv_bfloat16* __restrict__ Ol)
{
  extern __shared__ __align__(1024) char smem[];
  const int tid = threadIdx.x, lane = tid & 31, warp = tid >> 5;
  const int b = blockIdx.z, h = blockIdx.y, q0 = blockIdx.x * 128;
  const size_t baseq = ((size_t)b * 2048) * 3072 + h * 64;
  const size_t baseo = ((size_t)b * 2048) * 1024 + h * 64;
  const uint32_t aQ = s2u(smem);
  const uint32_t aKV = aQ + 32768;
  const int wm = warp * 16;

  const int rowA = lane & 15;
  const int kbA  = (lane & 16) ? 16 : 0;
  const int rowB = (lane & 7) + ((lane & 16) ? 8 : 0);
  const int kbB  = (lane & 8) ? 16 : 0;
  const int kvr  = lane & 15;
  const int ncb  = (lane & 16) ? 8 : 0;

  // ---- preload Q ----
  #pragma unroll
  for (int i = 0; i < 4; i++){
    int gg = tid + 256*i;
    int r = gg >> 3, c = gg & 7;
    uint32_t d = SWZ((uint32_t)(r*128 + c*16));
    const size_t src = baseq + (size_t)(q0 + r) * 3072 + c*8;
    cpasync16(aQ + d, QKVh + src);
    cpasync16(aQ + 16384 + d, QKVl + src);
  }
  CP_COMMIT();

  #define ISSUEKV(j) do { \
    uint32_t _st = aKV + ((j) & 1) * 32768; \
    int _j0 = (j) * 64; \
    _Pragma("unroll") \
    for (int _i = 0; _i < 2; _i++){ \
      int _gg = tid + 256*_i; \
      int _r = _gg >> 3, _c = _gg & 7; \
      uint32_t _d = SWZ((uint32_t)(_r*128 + _c*16)); \
      const size_t _srcK = baseq + 1024 + (size_t)(_j0 + _r) * 3072 + _c*8; \
      const size_t _srcV = baseq + 2048 + (size_t)(_j0 + _r) * 3072 + _c*8; \
      cpasync16(_st + _d,         QKVh + _srcK); \
      cpasync16(_st + 8192 + _d,  QKVl + _srcK); \
      cpasync16(_st + 16384 + _d, QKVh + _srcV); \
      cpasync16(_st + 24576 + _d, QKVl + _srcV); \
    } \
    CP_COMMIT(); \
  } while(0)

  ISSUEKV(0);
  CP_WAIT1();
  __syncthreads();

  uint32_t qfh[4][4], qfl[4][4];
  #pragma unroll
  for (int s = 0; s < 4; s++){
    uint32_t off = SWZ((uint32_t)((wm + rowA)*128 + s*32 + kbA));
    ldsm4(qfh[s], aQ + off);
    ldsm4(qfl[s], aQ + 16384 + off);
  }

  float m0 = -1e30f, m1 = -1e30f, l0 = 0.f, l1 = 0.f;
  float oa[8][4];
  #pragma unroll
  for (int nb = 0; nb < 8; nb++)
    #pragma unroll
    for (int r = 0; r < 4; r++) oa[nb][r] = 0.f;

  #pragma unroll 1
  for (int jt = 0; jt < 32; jt++){
    if (jt + 1 < 32){ ISSUEKV(jt + 1); CP_WAIT1(); }
    else            { CP_WAIT0(); }
    __syncthreads();
    const uint32_t st = aKV + (jt & 1) * 32768;

    float sc[8][4];
    #pragma unroll
    for (int nb = 0; nb < 8; nb++)
      #pragma unroll
      for (int r = 0; r < 4; r++) sc[nb][r] = 0.f;
    #pragma unroll
    for (int s = 0; s < 4; s++){
      #pragma unroll
      for (int g = 0; g < 4; g++){
        uint32_t off = SWZ((uint32_t)((g*16 + rowB)*128 + s*32 + kbB));
        uint32_t kh4[4], kl4[4];
        ldsm4(kh4, st + off);
        ldsm4(kl4, st + 8192 + off);
        mma16816(sc[2*g],   qfh[s], kh4);
        mma16816(sc[2*g+1], qfh[s], kh4 + 2);
        mma16816(sc[2*g],   qfl[s], kh4);
        mma16816(sc[2*g+1], qfl[s], kh4 + 2);
        mma16816(sc[2*g],   qfh[s], kl4);
        mma16816(sc[2*g+1], qfh[s], kl4 + 2);
      }
    }

    float mx0 = -1e30f, mx1 = -1e30f;
    #pragma unroll
    for (int nb = 0; nb < 8; nb++){
      sc[nb][0] *= 8.f; sc[nb][1] *= 8.f; sc[nb][2] *= 8.f; sc[nb][3] *= 8.f;
      mx0 = fmaxf(mx0, fmaxf(sc[nb][0], sc[nb][1]));
      mx1 = fmaxf(mx1, fmaxf(sc[nb][2], sc[nb][3]));
    }
    mx0 = fmaxf(mx0, __shfl_xor_sync(0xffffffffu, mx0, 1));
    mx0 = fmaxf(mx0, __shfl_xor_sync(0xffffffffu, mx0, 2));
    mx1 = fmaxf(mx1, __shfl_xor_sync(0xffffffffu, mx1, 1));
    mx1 = fmaxf(mx1, __shfl_xor_sync(0xffffffffu, mx1, 2));
    float nm0 = fmaxf(m0, mx0), nm1 = fmaxf(m1, mx1);
    float a0 = __expf(m0 - nm0), a1 = __expf(m1 - nm1);
    m0 = nm0; m1 = nm1;

    float rs0 = 0.f, rs1 = 0.f;
    uint32_t pfh[4][4], pfl[4][4];
    #pragma unroll
    for (int nb = 0; nb < 8; nb++){
      float p00 = __expf(sc[nb][0] - nm0), p01 = __expf(sc[nb][1] - nm0);
      float p10 = __expf(sc[nb][2] - nm1), p11 = __expf(sc[nb][3] - nm1);
      rs0 += p00 + p01; rs1 += p10 + p11;
      __nv_bfloat162 h0 = __floats2bfloat162_rn(p00, p01);
      __nv_bfloat162 h1 = __floats2bfloat162_rn(p10, p11);
      __nv_bfloat162 lo0 = __floats2bfloat162_rn(p00 - __bfloat162float(h0.x),
                                                 p01 - __bfloat162float(h0.y));
      __nv_bfloat162 lo1 = __floats2bfloat162_rn(p10 - __bfloat162float(h1.x),
                                                 p11 - __bfloat162float(h1.y));
      int j = nb >> 1, rq = (nb & 1) * 2;
      pfh[j][rq]   = *(uint32_t*)&h0;  pfh[j][rq+1] = *(uint32_t*)&h1;
      pfl[j][rq]   = *(uint32_t*)&lo0; pfl[j][rq+1] = *(uint32_t*)&lo1;
    }
    rs0 += __shfl_xor_sync(0xffffffffu, rs0, 1);
    rs0 += __shfl_xor_sync(0xffffffffu, rs0, 2);
    rs1 += __shfl_xor_sync(0xffffffffu, rs1, 1);
    rs1 += __shfl_xor_sync(0xffffffffu, rs1, 2);
    l0 = l0 * a0 + rs0; l1 = l1 * a1 + rs1;
    #pragma unroll
    for (int nb = 0; nb < 8; nb++){
      oa[nb][0] *= a0; oa[nb][1] *= a0; oa[nb][2] *= a1; oa[nb][3] *= a1;
    }

    #pragma unroll
    for (int s = 0; s < 4; s++){
      #pragma unroll
      for (int g = 0; g < 4; g++){
        uint32_t off = SWZ((uint32_t)((s*16 + kvr)*128 + (g*16 + ncb)*2));
        uint32_t vh4[4], vl4[4];
        ldsm4t(vh4, st + 16384 + off);
        ldsm4t(vl4, st + 24576 + off);
        mma16816(oa[2*g],   pfh[s], vh4);
        mma16816(oa[2*g+1], pfh[s], vh4 + 2);
        mma16816(oa[2*g],   pfl[s], vh4);
        mma16816(oa[2*g+1], pfl[s], vh4 + 2);
        mma16816(oa[2*g],   pfh[s], vl4);
        mma16816(oa[2*g+1], pfh[s], vl4 + 2);
      }
    }
    __syncthreads();
  }

  const int er = lane >> 2, ec = (lane & 3) * 2;
  float i0 = 1.0f / l0, i1 = 1.0f / l1;
  const int r0 = q0 + wm + er;
  #pragma unroll
  for (int nb = 0; nb < 8; nb++){
    int col = nb*8 + ec;
    float v0 = oa[nb][0]*i0, v1 = oa[nb][1]*i0;
    float v2 = oa[nb][2]*i1, v3 = oa[nb][3]*i1;
    __nv_bfloat162 h0 = __floats2bfloat162_rn(v0, v1);
    __nv_bfloat162 h1 = __floats2bfloat162_rn(v2, v3);
    __nv_bfloat162 lo0 = __floats2bfloat162_rn(v0 - __bfloat162float(h0.x),
                                               v1 - __bfloat162float(h0.y));
    __nv_bfloat162 lo1 = __floats2bfloat162_rn(v2 - __bfloat162float(h1.x),
                                               v3 - __bfloat162float(h1.y));
    size_t i0x = baseo + (size_t)r0 * 1024 + col;
    size_t i1x = baseo + (size_t)(r0 + 8) * 1024 + col;
    *(__nv_bfloat162*)(Oh + i0x) = h0;
    *(__nv_bfloat162*)(Ol + i0x) = lo0;
    *(__nv_bfloat162*)(Oh + i1x) = h1;
    *(__nv_bfloat162*)(Ol + i1x) = lo1;
  }
  #undef ISSUEKV
}

// ======================= launch =======================
extern "C" void kernel_launch(void* const* d_in, const int* in_sizes, int n_in,
                              void* d_out, int out_size)
{
  (void)in_sizes; (void)n_in; (void)out_size;
  const float* x   = (const float*)d_in[0];
  const float* Wk  = (const float*)d_in[2];
  const float* Wq  = (const float*)d_in[3];
  const float* Wv  = (const float*)d_in[4];
  const float* Wfc = (const float*)d_in[5];
  const float* bfc = (const float*)d_in[6];
  const float* g1  = (const float*)d_in[7];
  const float* b1  = (const float*)d_in[8];
  const float* g2  = (const float*)d_in[9];
  const float* b2  = (const float*)d_in[10];
  const float* W1  = (const float*)d_in[11];
  const float* bf1 = (const float*)d_in[12];
  const float* W2  = (const float*)d_in[13];
  const float* bf2 = (const float*)d_in[14];
  float* out = (float*)d_out;

  __nv_bfloat16 *xlh,*xll,*qkvh,*qkvl,*oh,*ol,*hh,*hl;
  __nv_bfloat16 *wqkvh,*wqkvl,*wfh,*wfl,*w1h,*w1l,*w2h,*w2l;
  float *x2;
  cudaGetSymbolAddress((void**)&xlh, g_xlh); cudaGetSymbolAddress((void**)&xll, g_xll);
  cudaGetSymbolAddress((void**)&qkvh, g_qkvh); cudaGetSymbolAddress((void**)&qkvl, g_qkvl);
  cudaGetSymbolAddress((void**)&oh, g_oh); cudaGetSymbolAddress((void**)&ol, g_ol);
  cudaGetSymbolAddress((void**)&x2, g_x2);
  cudaGetSymbolAddress((void**)&hh, g_hh); cudaGetSymbolAddress((void**)&hl, g_hl);
  cudaGetSymbolAddress((void**)&wqkvh, g_wqkvh); cudaGetSymbolAddress((void**)&wqkvl, g_wqkvl);
  cudaGetSymbolAddress((void**)&wfh, g_wfh); cudaGetSymbolAddress((void**)&wfl, g_wfl);
  cudaGetSymbolAddress((void**)&w1h, g_w1h); cudaGetSymbolAddress((void**)&w1l, g_w1l);
  cudaGetSymbolAddress((void**)&w2h, g_w2h); cudaGetSymbolAddress((void**)&w2l, g_w2l);

  static int smem_set = 0;
  if (!smem_set){
    cudaFuncSetAttribute(gemm_mma, cudaFuncAttributeMaxDynamicSharedMemorySize, 147456);
    cudaFuncSetAttribute(attn_mma, cudaFuncAttributeMaxDynamicSharedMemorySize, 98304);
    smem_set = 1;
  }

  const int M = 8192, D = 1024;
  const int GSM = 147456;   // 3 stages x 48KB
  const int ASM = 98304;
  dim3 tb(32, 8);
  dim3 tD(D/32, D/32);

  // QKV weights into fused [3072, 1024] buffer (rows: Q 0-1023, K 1024-2047, V 2048-3071)
  transp_split<<<tD, tb>>>(Wq, wqkvh,           wqkvl,           D, D);
  transp_split<<<tD, tb>>>(Wk, wqkvh + DD*DD,   wqkvl + DD*DD,   D, D);
  transp_split<<<tD, tb>>>(Wv, wqkvh + 2*DD*DD, wqkvl + 2*DD*DD, D, D);
  transp_split<<<tD, tb>>>(Wfc, wfh, wfl, D, D);
  transp_split<<<dim3(4*D/32, D/32), tb>>>(W1, w1h, w1l, D, 4*D);
  transp_split<<<dim3(D/32, 4*D/32), tb>>>(W2, w2h, w2l, 4*D, D);

  dim3 gQKV(3*D/256, M/128);   // (12, 64)
  dim3 gD(D/256, M/128);       // (4, 64)
  dim3 gF(4*D/256, M/128);     // (16, 64)

  ln1024_split<<<M, 256>>>(x, g1, b1, xlh, xll);
  gemm_mma<<<gQKV, 256, GSM>>>(xlh, xll, wqkvh, wqkvl, nullptr, nullptr, nullptr,
                               qkvh, qkvl, M, 3*D, D, 0, 1);
  attn_mma<<<dim3(16, 16, 4), 256, ASM>>>(qkvh, qkvl, oh, ol);
  gemm_mma<<<gD, 256, GSM>>>(oh, ol, wfh, wfl, bfc, x, x2, nullptr, nullptr,
                             M, D, D, 0, 0);
  ln1024_split<<<M, 256>>>(x2, g2, b2, xlh, xll);
  gemm_mma<<<gF, 256, GSM>>>(xlh, xll, w1h, w1l, bf1, nullptr, nullptr, hh, hl,
                             M, 4*D, D, 1, 1);
  gemm_mma<<<gD, 256, GSM>>>(hh, hl, w2h, w2l, bf2, x2, out, nullptr, nullptr,
                             M, D, 4*D, 0, 0);
}

// round 7
// speedup vs baseline: 3.5955x; 1.0890x over previous
#include <cuda_runtime.h>
#include <cuda_bf16.h>
#include <cstdint>

typedef unsigned long long ull;

// ---- PTX helpers (portable sm_80+) ----
__device__ __forceinline__ uint32_t s2u(const void* p){
  uint32_t a; asm("{ .reg .u64 t; cvta.to.shared.u64 t, %1; cvt.u32.u64 %0, t; }"
                  : "=r"(a) : "l"(p));
  return a;
}
__device__ __forceinline__ void ldsm4(uint32_t* r, uint32_t a){
  asm volatile("ldmatrix.sync.aligned.m8n8.x4.shared.b16 {%0,%1,%2,%3}, [%4];"
               : "=r"(r[0]), "=r"(r[1]), "=r"(r[2]), "=r"(r[3]) : "r"(a));
}
__device__ __forceinline__ void ldsm4t(uint32_t* r, uint32_t a){
  asm volatile("ldmatrix.sync.aligned.m8n8.x4.trans.shared.b16 {%0,%1,%2,%3}, [%4];"
               : "=r"(r[0]), "=r"(r[1]), "=r"(r[2]), "=r"(r[3]) : "r"(a));
}
__device__ __forceinline__ void mma16816(float* d, const uint32_t* a, const uint32_t* b){
  asm volatile(
    "mma.sync.aligned.m16n8k16.row.col.f32.bf16.bf16.f32 "
    "{%0,%1,%2,%3}, {%4,%5,%6,%7}, {%8,%9}, {%0,%1,%2,%3};"
    : "+f"(d[0]), "+f"(d[1]), "+f"(d[2]), "+f"(d[3])
    : "r"(a[0]), "r"(a[1]), "r"(a[2]), "r"(a[3]), "r"(b[0]), "r"(b[1]));
}
__device__ __forceinline__ void cpasync16(uint32_t dst, const void* src){
  asm volatile("cp.async.cg.shared.global [%0], [%1], 16;" :: "r"(dst), "l"(src) : "memory");
}
#define CP_COMMIT() asm volatile("cp.async.commit_group;" ::: "memory")
#define CP_WAIT1()  asm volatile("cp.async.wait_group 1;" ::: "memory")
#define CP_WAIT0()  asm volatile("cp.async.wait_group 0;" ::: "memory")

#define SWZ(o) ((o) ^ (((o) >> 3) & 0x70))

// ======================= scratch (device globals) =======================
#define MR 8192
#define DD 1024
__device__ __nv_bfloat16 g_xlh[MR*DD], g_xll[MR*DD];
__device__ __nv_bfloat16 g_qkvh[MR*3*DD], g_qkvl[MR*3*DD];
__device__ __nv_bfloat16 g_oh[MR*DD], g_ol[MR*DD];
__device__ float g_x2[MR*DD];
__device__ __nv_bfloat16 g_hh[MR*4*DD], g_hl[MR*4*DD];
__device__ __nv_bfloat16 g_wqkvh[3*DD*DD], g_wqkvl[3*DD*DD];
__device__ __nv_bfloat16 g_wfh[DD*DD], g_wfl[DD*DD];
__device__ __nv_bfloat16 g_w1h[4*DD*DD], g_w1l[4*DD*DD];
__device__ __nv_bfloat16 g_w2h[4*DD*DD], g_w2l[4*DD*DD];

// ======================= LayerNorm -> bf16 hi/lo =======================
__global__ __launch_bounds__(256) void ln1024_split(
    const float* __restrict__ x, const float* __restrict__ g,
    const float* __restrict__ bt, __nv_bfloat16* __restrict__ yh,
    __nv_bfloat16* __restrict__ yl)
{
  int row = blockIdx.x;
  const float4* xr = (const float4*)(x + (size_t)row * 1024);
  float4 v = xr[threadIdx.x];
  float s = v.x + v.y + v.z + v.w;
  float q = v.x*v.x + v.y*v.y + v.z*v.z + v.w*v.w;
  #pragma unroll
  for (int off = 16; off; off >>= 1){
    s += __shfl_xor_sync(0xffffffffu, s, off);
    q += __shfl_xor_sync(0xffffffffu, q, off);
  }
  __shared__ float ss[8], qs[8];
  int w = threadIdx.x >> 5;
  if ((threadIdx.x & 31) == 0){ ss[w] = s; qs[w] = q; }
  __syncthreads();
  s = ss[0]+ss[1]+ss[2]+ss[3]+ss[4]+ss[5]+ss[6]+ss[7];
  q = qs[0]+qs[1]+qs[2]+qs[3]+qs[4]+qs[5]+qs[6]+qs[7];
  float mu   = s * (1.0f/1024.0f);
  float var  = q * (1.0f/1024.0f) - mu*mu;
  float rstd = rsqrtf(var + 1e-5f);
  int c = threadIdx.x * 4;
  float4 gg = *(const float4*)(g  + c);
  float4 bb = *(const float4*)(bt + c);
  float o0 = (v.x-mu)*rstd*gg.x + bb.x;
  float o1 = (v.y-mu)*rstd*gg.y + bb.y;
  float o2 = (v.z-mu)*rstd*gg.z + bb.z;
  float o3 = (v.w-mu)*rstd*gg.w + bb.w;
  __nv_bfloat16 h0=__float2bfloat16(o0), h1=__float2bfloat16(o1);
  __nv_bfloat16 h2=__float2bfloat16(o2), h3=__float2bfloat16(o3);
  __nv_bfloat162 ph0; ph0.x=h0; ph0.y=h1;
  __nv_bfloat162 ph1; ph1.x=h2; ph1.y=h3;
  __nv_bfloat162 pl0; pl0.x=__float2bfloat16(o0-__bfloat162float(h0));
                      pl0.y=__float2bfloat16(o1-__bfloat162float(h1));
  __nv_bfloat162 pl1; pl1.x=__float2bfloat16(o2-__bfloat162float(h2));
                      pl1.y=__float2bfloat16(o3-__bfloat162float(h3));
  size_t idx = (size_t)row*1024 + c;
  *(__nv_bfloat162*)(yh+idx)   = ph0; *(__nv_bfloat162*)(yh+idx+2) = ph1;
  *(__nv_bfloat162*)(yl+idx)   = pl0; *(__nv_bfloat162*)(yl+idx+2) = pl1;
}

// ======================= weight transpose + split =======================
__global__ void transp_split(const float* __restrict__ W,
                             __nv_bfloat16* __restrict__ Th,
                             __nv_bfloat16* __restrict__ Tl, int K, int N)
{
  __shared__ float t[32][33];
  int n0 = blockIdx.x*32, k0 = blockIdx.y*32;
  int tx = threadIdx.x, ty = threadIdx.y; // 32 x 8
  #pragma unroll
  for (int j = 0; j < 4; j++)
    t[ty+8*j][tx] = W[(size_t)(k0+ty+8*j)*N + n0+tx];
  __syncthreads();
  #pragma unroll
  for (int j = 0; j < 4; j++){
    float v = t[tx][ty+8*j];
    __nv_bfloat16 h = __float2bfloat16(v);
    size_t idx = (size_t)(n0+ty+8*j)*K + k0+tx;
    Th[idx] = h;
    Tl[idx] = __float2bfloat16(v - __bfloat162float(h));
  }
}

// ======================= split-bf16 GEMM: single K pass, interleaved 3 terms ======
// CTA 128x256, 8 warps x 64x64. Per K-chunk, stage holds Ah|Al|Bh|Bl (96KB);
// 2 stages (192KB smem). Terms per chunk: Ah*Bh + Ah*Bl + Al*Bh.
__global__ __launch_bounds__(256, 1) void gemm_mma(
    const __nv_bfloat16* __restrict__ Ahi, const __nv_bfloat16* __restrict__ Alo,
    const __nv_bfloat16* __restrict__ Bhi, const __nv_bfloat16* __restrict__ Blo,
    const float* __restrict__ bias, const float* __restrict__ res,
    float* __restrict__ C, __nv_bfloat16* __restrict__ Chi,
    __nv_bfloat16* __restrict__ Clo,
    int M, int N, int K, int relu, int split)
{
  extern __shared__ __align__(1024) char smem[];
  const int tid = threadIdx.x, lane = tid & 31, wid = tid >> 5;
  const int m0 = blockIdx.y * 128, n0 = blockIdx.x * 256;
  const int wm = (wid >> 2) * 64, wn = (wid & 3) * 64;
  const uint32_t aS0 = s2u(smem);   // stage: Ah 16K | Al 16K | Bh 32K | Bl 32K = 96K

  const int nc = K >> 6;            // single pass over K

  float acc[4][8][4];
  #pragma unroll
  for (int i = 0; i < 4; i++)
    #pragma unroll
    for (int j = 0; j < 8; j++)
      #pragma unroll
      for (int r = 0; r < 4; r++) acc[i][j][r] = 0.f;

  const int rowA = lane & 15;
  const int kbA  = (lane & 16) ? 16 : 0;
  const int rowB = (lane & 7) + ((lane & 16) ? 8 : 0);
  const int kbB  = (lane & 8) ? 16 : 0;

  #define ISSUE(c) do { \
    int _k0 = (c) << 6; \
    uint32_t _st = aS0 + ((c) & 1) * 98304; \
    _Pragma("unroll") \
    for (int _i = 0; _i < 4; _i++){ \
      int _gg = tid + 256*_i; int _r = _gg >> 3, _c = _gg & 7; \
      uint32_t _d = SWZ((uint32_t)(_r*128 + _c*16)); \
      const size_t _src = (size_t)(m0 + _r) * K + _k0 + _c*8; \
      cpasync16(_st + _d,         Ahi + _src); \
      cpasync16(_st + 16384 + _d, Alo + _src); \
    } \
    _Pragma("unroll") \
    for (int _i = 0; _i < 8; _i++){ \
      int _gg = tid + 256*_i; int _r = _gg >> 3, _c = _gg & 7; \
      uint32_t _d = SWZ((uint32_t)(_r*128 + _c*16)); \
      const size_t _src = (size_t)(n0 + _r) * K + _k0 + _c*8; \
      cpasync16(_st + 32768 + _d, Bhi + _src); \
      cpasync16(_st + 65536 + _d, Blo + _src); \
    } \
    CP_COMMIT(); \
  } while(0)

  ISSUE(0);
  for (int c = 0; c < nc; c++){
    CP_WAIT0();            // only group c pending at this point
    __syncthreads();       // prior compute on the other stage is done
    if (c + 1 < nc) ISSUE(c + 1);   // overlaps with compute below
    const uint32_t st = aS0 + (c & 1) * 98304;
    #pragma unroll
    for (int s = 0; s < 4; s++){
      uint32_t ah[4][4], bh[4][4];
      #pragma unroll
      for (int mi = 0; mi < 4; mi++){
        uint32_t off = (uint32_t)((wm + mi*16 + rowA)*128 + s*32 + kbA);
        ldsm4(ah[mi], st + SWZ(off));
      }
      #pragma unroll
      for (int njp = 0; njp < 4; njp++){
        uint32_t off = (uint32_t)((wn + njp*16 + rowB)*128 + s*32 + kbB);
        ldsm4(bh[njp], st + 32768 + SWZ(off));
      }
      #pragma unroll
      for (int mi = 0; mi < 4; mi++)
        #pragma unroll
        for (int nj = 0; nj < 8; nj++)
          mma16816(acc[mi][nj], ah[mi], &bh[nj >> 1][(nj & 1) * 2]);
      // term 2: Ah * Bl
      uint32_t bl[4][4];
      #pragma unroll
      for (int njp = 0; njp < 4; njp++){
        uint32_t off = (uint32_t)((wn + njp*16 + rowB)*128 + s*32 + kbB);
        ldsm4(bl[njp], st + 65536 + SWZ(off));
      }
      #pragma unroll
      for (int mi = 0; mi < 4; mi++)
        #pragma unroll
        for (int nj = 0; nj < 8; nj++)
          mma16816(acc[mi][nj], ah[mi], &bl[nj >> 1][(nj & 1) * 2]);
      // term 3: Al * Bh
      uint32_t al[4][4];
      #pragma unroll
      for (int mi = 0; mi < 4; mi++){
        uint32_t off = (uint32_t)((wm + mi*16 + rowA)*128 + s*32 + kbA);
        ldsm4(al[mi], st + 16384 + SWZ(off));
      }
      #pragma unroll
      for (int mi = 0; mi < 4; mi++)
        #pragma unroll
        for (int nj = 0; nj < 8; nj++)
          mma16816(acc[mi][nj], al[mi], &bh[nj >> 1][(nj & 1) * 2]);
    }
  }
  #undef ISSUE

  const int er = lane >> 2, ec = (lane & 3) * 2;
  #pragma unroll
  for (int mi = 0; mi < 4; mi++){
    #pragma unroll
    for (int half = 0; half < 2; half++){
      int row = m0 + wm + mi*16 + er + half*8;
      #pragma unroll
      for (int nj = 0; nj < 8; nj++){
        int col = n0 + wn + nj*8 + ec;
        float v0 = acc[mi][nj][half*2 + 0];
        float v1 = acc[mi][nj][half*2 + 1];
        if (bias){
          float2 bv = *(const float2*)(bias + col);
          v0 += bv.x; v1 += bv.y;
        }
        if (relu){ v0 = fmaxf(v0, 0.f); v1 = fmaxf(v1, 0.f); }
        if (res){
          float2 rv = *(const float2*)(res + (size_t)row*N + col);
          v0 += rv.x; v1 += rv.y;
        }
        size_t idx = (size_t)row*N + col;
        if (split){
          __nv_bfloat16 h0 = __float2bfloat16(v0), h1 = __float2bfloat16(v1);
          __nv_bfloat162 ph; ph.x = h0; ph.y = h1;
          __nv_bfloat162 pl;
          pl.x = __float2bfloat16(v0 - __bfloat162float(h0));
          pl.y = __float2bfloat16(v1 - __bfloat162float(h1));
          *(__nv_bfloat162*)(Chi + idx) = ph;
          *(__nv_bfloat162*)(Clo + idx) = pl;
        } else {
          float2 o; o.x = v0; o.y = v1;
          *(float2*)(C + idx) = o;
        }
      }
    }
  }
}

// ======================= flash attention via HMMA, split-bf16 =======================
// QKV fused buffer [rows, 3072]: Q at col 0, K at 1024, V at 2048 (head h -> +h*64).
__global__ __launch_bounds__(256, 1) void attn_mma(
    const __nv_bfloat16* __restrict__ QKVh, const __nv_bfloat16* __restrict__ QKVl,
    __nv_bfloat16* __restrict__ Oh, __nv_bfloat16* __restrict__ Ol)
{
  extern __shared__ __align__(1024) char smem[];
  const int tid = threadIdx.x, lane = tid & 31, warp = tid >> 5;
  const int b = blockIdx.z, h = blockIdx.y, q0 = blockIdx.x * 128;
  const size_t baseq = ((size_t)b * 2048) * 3072 + h * 64;
  const size_t baseo = ((size_t)b * 2048) * 1024 + h * 64;
  const uint32_t aQ = s2u(smem);
  const uint32_t aKV = aQ + 32768;
  const int wm = warp * 16;

  const int rowA = lane & 15;
  const int kbA  = (lane & 16) ? 16 : 0;
  const int rowB = (lane & 7) + ((lane & 16) ? 8 : 0);
  const int kbB  = (lane & 8) ? 16 : 0;
  const int kvr  = lane & 15;
  const int ncb  = (lane & 16) ? 8 : 0;

  // ---- preload Q ----
  #pragma unroll
  for (int i = 0; i < 4; i++){
    int gg = tid + 256*i;
    int r = gg >> 3, c = gg & 7;
    uint32_t d = SWZ((uint32_t)(r*128 + c*16));
    const size_t src = baseq + (size_t)(q0 + r) * 3072 + c*8;
    cpasync16(aQ + d, QKVh + src);
    cpasync16(aQ + 16384 + d, QKVl + src);
  }
  CP_COMMIT();

  #define ISSUEKV(j) do { \
    uint32_t _st = aKV + ((j) & 1) * 32768; \
    int _j0 = (j) * 64; \
    _Pragma("unroll") \
    for (int _i = 0; _i < 2; _i++){ \
      int _gg = tid + 256*_i; \
      int _r = _gg >> 3, _c = _gg & 7; \
      uint32_t _d = SWZ((uint32_t)(_r*128 + _c*16)); \
      const size_t _srcK = baseq + 1024 + (size_t)(_j0 + _r) * 3072 + _c*8; \
      const size_t _srcV = baseq + 2048 + (size_t)(_j0 + _r) * 3072 + _c*8; \
      cpasync16(_st + _d,         QKVh + _srcK); \
      cpasync16(_st + 8192 + _d,  QKVl + _srcK); \
      cpasync16(_st + 16384 + _d, QKVh + _srcV); \
      cpasync16(_st + 24576 + _d, QKVl + _srcV); \
    } \
    CP_COMMIT(); \
  } while(0)

  ISSUEKV(0);
  CP_WAIT1();
  __syncthreads();

  uint32_t qfh[4][4], qfl[4][4];
  #pragma unroll
  for (int s = 0; s < 4; s++){
    uint32_t off = SWZ((uint32_t)((wm + rowA)*128 + s*32 + kbA));
    ldsm4(qfh[s], aQ + off);
    ldsm4(qfl[s], aQ + 16384 + off);
  }

  float m0 = -1e30f, m1 = -1e30f, l0 = 0.f, l1 = 0.f;
  float oa[8][4];
  #pragma unroll
  for (int nb = 0; nb < 8; nb++)
    #pragma unroll
    for (int r = 0; r < 4; r++) oa[nb][r] = 0.f;

  #pragma unroll 1
  for (int jt = 0; jt < 32; jt++){
    if (jt + 1 < 32){ ISSUEKV(jt + 1); CP_WAIT1(); }
    else            { CP_WAIT0(); }
    __syncthreads();
    const uint32_t st = aKV + (jt & 1) * 32768;

    float sc[8][4];
    #pragma unroll
    for (int nb = 0; nb < 8; nb++)
      #pragma unroll
      for (int r = 0; r < 4; r++) sc[nb][r] = 0.f;
    #pragma unroll
    for (int s = 0; s < 4; s++){
      #pragma unroll
      for (int g = 0; g < 4; g++){
        uint32_t off = SWZ((uint32_t)((g*16 + rowB)*128 + s*32 + kbB));
        uint32_t kh4[4], kl4[4];
        ldsm4(kh4, st + off);
        ldsm4(kl4, st + 8192 + off);
        mma16816(sc[2*g],   qfh[s], kh4);
        mma16816(sc[2*g+1], qfh[s], kh4 + 2);
        mma16816(sc[2*g],   qfl[s], kh4);
        mma16816(sc[2*g+1], qfl[s], kh4 + 2);
        mma16816(sc[2*g],   qfh[s], kl4);
        mma16816(sc[2*g+1], qfh[s], kl4 + 2);
      }
    }

    float mx0 = -1e30f, mx1 = -1e30f;
    #pragma unroll
    for (int nb = 0; nb < 8; nb++){
      sc[nb][0] *= 8.f; sc[nb][1] *= 8.f; sc[nb][2] *= 8.f; sc[nb][3] *= 8.f;
      mx0 = fmaxf(mx0, fmaxf(sc[nb][0], sc[nb][1]));
      mx1 = fmaxf(mx1, fmaxf(sc[nb][2], sc[nb][3]));
    }
    mx0 = fmaxf(mx0, __shfl_xor_sync(0xffffffffu, mx0, 1));
    mx0 = fmaxf(mx0, __shfl_xor_sync(0xffffffffu, mx0, 2));
    mx1 = fmaxf(mx1, __shfl_xor_sync(0xffffffffu, mx1, 1));
    mx1 = fmaxf(mx1, __shfl_xor_sync(0xffffffffu, mx1, 2));
    float nm0 = fmaxf(m0, mx0), nm1 = fmaxf(m1, mx1);
    float a0 = __expf(m0 - nm0), a1 = __expf(m1 - nm1);
    m0 = nm0; m1 = nm1;

    float rs0 = 0.f, rs1 = 0.f;
    uint32_t pfh[4][4], pfl[4][4];
    #pragma unroll
    for (int nb = 0; nb < 8; nb++){
      float p00 = __expf(sc[nb][0] - nm0), p01 = __expf(sc[nb][1] - nm0);
      float p10 = __expf(sc[nb][2] - nm1), p11 = __expf(sc[nb][3] - nm1);
      rs0 += p00 + p01; rs1 += p10 + p11;
      __nv_bfloat162 h0 = __floats2bfloat162_rn(p00, p01);
      __nv_bfloat162 h1 = __floats2bfloat162_rn(p10, p11);
      __nv_bfloat162 lo0 = __floats2bfloat162_rn(p00 - __bfloat162float(h0.x),
                                                 p01 - __bfloat162float(h0.y));
      __nv_bfloat162 lo1 = __floats2bfloat162_rn(p10 - __bfloat162float(h1.x),
                                                 p11 - __bfloat162float(h1.y));
      int j = nb >> 1, rq = (nb & 1) * 2;
      pfh[j][rq]   = *(uint32_t*)&h0;  pfh[j][rq+1] = *(uint32_t*)&h1;
      pfl[j][rq]   = *(uint32_t*)&lo0; pfl[j][rq+1] = *(uint32_t*)&lo1;
    }
    rs0 += __shfl_xor_sync(0xffffffffu, rs0, 1);
    rs0 += __shfl_xor_sync(0xffffffffu, rs0, 2);
    rs1 += __shfl_xor_sync(0xffffffffu, rs1, 1);
    rs1 += __shfl_xor_sync(0xffffffffu, rs1, 2);
    l0 = l0 * a0 + rs0; l1 = l1 * a1 + rs1;
    #pragma unroll
    for (int nb = 0; nb < 8; nb++){
      oa[nb][0] *= a0; oa[nb][1] *= a0; oa[nb][2] *= a1; oa[nb][3] *= a1;
    }

    #pragma unroll
    for (int s = 0; s < 4; s++){
      #pragma unroll
      for (int g = 0; g < 4; g++){
        uint32_t off = SWZ((uint32_t)((s*16 + kvr)*128 + (g*16 + ncb)*2));
        uint32_t vh4[4], vl4[4];
        ldsm4t(vh4, st + 16384 + off);
        ldsm4t(vl4, st + 24576 + off);
        mma16816(oa[2*g],   pfh[s], vh4);
        mma16816(oa[2*g+1], pfh[s], vh4 + 2);
        mma16816(oa[2*g],   pfl[s], vh4);
        mma16816(oa[2*g+1], pfl[s], vh4 + 2);
        mma16816(oa[2*g],   pfh[s], vl4);
        mma16816(oa[2*g+1], pfh[s], vl4 + 2);
      }
    }
    __syncthreads();
  }

  const int er = lane >> 2, ec = (lane & 3) * 2;
  float i0 = 1.0f / l0, i1 = 1.0f / l1;
  const int r0 = q0 + wm + er;
  #pragma unroll
  for (int nb = 0; nb < 8; nb++){
    int col = nb*8 + ec;
    float v0 = oa[nb][0]*i0, v1 = oa[nb][1]*i0;
    float v2 = oa[nb][2]*i1, v3 = oa[nb][3]*i1;
    __nv_bfloat162 h0 = __floats2bfloat162_rn(v0, v1);
    __nv_bfloat162 h1 = __floats2bfloat162_rn(v2, v3);
    __nv_bfloat162 lo0 = __floats2bfloat162_rn(v0 - __bfloat162float(h0.x),
                                               v1 - __bfloat162float(h0.y));
    __nv_bfloat162 lo1 = __floats2bfloat162_rn(v2 - __bfloat162float(h1.x),
                                               v3 - __bfloat162float(h1.y));
    size_t i0x = baseo + (size_t)r0 * 1024 + col;
    size_t i1x = baseo + (size_t)(r0 + 8) * 1024 + col;
    *(__nv_bfloat162*)(Oh + i0x) = h0;
    *(__nv_bfloat162*)(Ol + i0x) = lo0;
    *(__nv_bfloat162*)(Oh + i1x) = h1;
    *(__nv_bfloat162*)(Ol + i1x) = lo1;
  }
  #undef ISSUEKV
}

// ======================= launch =======================
extern "C" void kernel_launch(void* const* d_in, const int* in_sizes, int n_in,
                              void* d_out, int out_size)
{
  (void)in_sizes; (void)n_in; (void)out_size;
  const float* x   = (const float*)d_in[0];
  const float* Wk  = (const float*)d_in[2];
  const float* Wq  = (const float*)d_in[3];
  const float* Wv  = (const float*)d_in[4];
  const float* Wfc = (const float*)d_in[5];
  const float* bfc = (const float*)d_in[6];
  const float* g1  = (const float*)d_in[7];
  const float* b1  = (const float*)d_in[8];
  const float* g2  = (const float*)d_in[9];
  const float* b2  = (const float*)d_in[10];
  const float* W1  = (const float*)d_in[11];
  const float* bf1 = (const float*)d_in[12];
  const float* W2  = (const float*)d_in[13];
  const float* bf2 = (const float*)d_in[14];
  float* out = (float*)d_out;

  __nv_bfloat16 *xlh,*xll,*qkvh,*qkvl,*oh,*ol,*hh,*hl;
  __nv_bfloat16 *wqkvh,*wqkvl,*wfh,*wfl,*w1h,*w1l,*w2h,*w2l;
  float *x2;
  cudaGetSymbolAddress((void**)&xlh, g_xlh); cudaGetSymbolAddress((void**)&xll, g_xll);
  cudaGetSymbolAddress((void**)&qkvh, g_qkvh); cudaGetSymbolAddress((void**)&qkvl, g_qkvl);
  cudaGetSymbolAddress((void**)&oh, g_oh); cudaGetSymbolAddress((void**)&ol, g_ol);
  cudaGetSymbolAddress((void**)&x2, g_x2);
  cudaGetSymbolAddress((void**)&hh, g_hh); cudaGetSymbolAddress((void**)&hl, g_hl);
  cudaGetSymbolAddress((void**)&wqkvh, g_wqkvh); cudaGetSymbolAddress((void**)&wqkvl, g_wqkvl);
  cudaGetSymbolAddress((void**)&wfh, g_wfh); cudaGetSymbolAddress((void**)&wfl, g_wfl);
  cudaGetSymbolAddress((void**)&w1h, g_w1h); cudaGetSymbolAddress((void**)&w1l, g_w1l);
  cudaGetSymbolAddress((void**)&w2h, g_w2h); cudaGetSymbolAddress((void**)&w2l, g_w2l);

  static int smem_set = 0;
  if (!smem_set){
    cudaFuncSetAttribute(gemm_mma, cudaFuncAttributeMaxDynamicSharedMemorySize, 196608);
    cudaFuncSetAttribute(attn_mma, cudaFuncAttributeMaxDynamicSharedMemorySize, 98304);
    smem_set = 1;
  }

  const int M = 8192, D = 1024;
  const int GSM = 196608;   // 2 stages x 96KB (Ah|Al|Bh|Bl)
  const int ASM = 98304;
  dim3 tb(32, 8);
  dim3 tD(D/32, D/32);

  // QKV weights into fused [3072, 1024] buffer (rows: Q 0-1023, K 1024-2047, V 2048-3071)
  transp_split<<<tD, tb>>>(Wq, wqkvh,           wqkvl,           D, D);
  transp_split<<<tD, tb>>>(Wk, wqkvh + DD*DD,   wqkvl + DD*DD,   D, D);
  transp_split<<<tD, tb>>>(Wv, wqkvh + 2*DD*DD, wqkvl + 2*DD*DD, D, D);
  transp_split<<<tD, tb>>>(Wfc, wfh, wfl, D, D);
  transp_split<<<dim3(4*D/32, D/32), tb>>>(W1, w1h, w1l, D, 4*D);
  transp_split<<<dim3(D/32, 4*D/32), tb>>>(W2, w2h, w2l, 4*D, D);

  dim3 gQKV(3*D/256, M/128);   // (12, 64)
  dim3 gD(D/256, M/128);       // (4, 64)
  dim3 gF(4*D/256, M/128);     // (16, 64)

  ln1024_split<<<M, 256>>>(x, g1, b1, xlh, xll);
  gemm_mma<<<gQKV, 256, GSM>>>(xlh, xll, wqkvh, wqkvl, nullptr, nullptr, nullptr,
                               qkvh, qkvl, M, 3*D, D, 0, 1);
  attn_mma<<<dim3(16, 16, 4), 256, ASM>>>(qkvh, qkvl, oh, ol);
  gemm_mma<<<gD, 256, GSM>>>(oh, ol, wfh, wfl, bfc, x, x2, nullptr, nullptr,
                             M, D, D, 0, 0);
  ln1024_split<<<M, 256>>>(x2, g2, b2, xlh, xll);
  gemm_mma<<<gF, 256, GSM>>>(xlh, xll, w1h, w1l, bf1, nullptr, nullptr, hh, hl,
                             M, 4*D, D, 1, 1);
  gemm_mma<<<gD, 256, GSM>>>(hh, hl, w2h, w2l, bf2, x2, out, nullptr, nullptr,
                             M, D, 4*D, 0, 0);
}

// round 8
// speedup vs baseline: 3.6416x; 1.0128x over previous
#include <cuda_runtime.h>
#include <cuda_bf16.h>
#include <cstdint>

typedef unsigned long long ull;

// ---- PTX helpers (portable sm_80+) ----
__device__ __forceinline__ uint32_t s2u(const void* p){
  uint32_t a; asm("{ .reg .u64 t; cvta.to.shared.u64 t, %1; cvt.u32.u64 %0, t; }"
                  : "=r"(a) : "l"(p));
  return a;
}
__device__ __forceinline__ void ldsm4(uint32_t* r, uint32_t a){
  asm volatile("ldmatrix.sync.aligned.m8n8.x4.shared.b16 {%0,%1,%2,%3}, [%4];"
               : "=r"(r[0]), "=r"(r[1]), "=r"(r[2]), "=r"(r[3]) : "r"(a));
}
__device__ __forceinline__ void ldsm4t(uint32_t* r, uint32_t a){
  asm volatile("ldmatrix.sync.aligned.m8n8.x4.trans.shared.b16 {%0,%1,%2,%3}, [%4];"
               : "=r"(r[0]), "=r"(r[1]), "=r"(r[2]), "=r"(r[3]) : "r"(a));
}
__device__ __forceinline__ void mma16816(float* d, const uint32_t* a, const uint32_t* b){
  asm volatile(
    "mma.sync.aligned.m16n8k16.row.col.f32.bf16.bf16.f32 "
    "{%0,%1,%2,%3}, {%4,%5,%6,%7}, {%8,%9}, {%0,%1,%2,%3};"
    : "+f"(d[0]), "+f"(d[1]), "+f"(d[2]), "+f"(d[3])
    : "r"(a[0]), "r"(a[1]), "r"(a[2]), "r"(a[3]), "r"(b[0]), "r"(b[1]));
}
__device__ __forceinline__ void cpasync16(uint32_t dst, const void* src){
  asm volatile("cp.async.cg.shared.global [%0], [%1], 16;" :: "r"(dst), "l"(src) : "memory");
}
#define CP_COMMIT() asm volatile("cp.async.commit_group;" ::: "memory")
#define CP_WAIT1()  asm volatile("cp.async.wait_group 1;" ::: "memory")
#define CP_WAIT0()  asm volatile("cp.async.wait_group 0;" ::: "memory")

#define SWZ(o) ((o) ^ (((o) >> 3) & 0x70))

// ======================= scratch (device globals) =======================
#define MR 8192
#define DD 1024
__device__ __nv_bfloat16 g_xlh[MR*DD], g_xll[MR*DD];
__device__ __nv_bfloat16 g_qkvh[MR*3*DD], g_qkvl[MR*3*DD];
__device__ __nv_bfloat16 g_oh[MR*DD], g_ol[MR*DD];
__device__ float g_x2[MR*DD];
__device__ __nv_bfloat16 g_hh[MR*4*DD], g_hl[MR*4*DD];
__device__ __nv_bfloat16 g_wqkvh[3*DD*DD], g_wqkvl[3*DD*DD];
__device__ __nv_bfloat16 g_wfh[DD*DD], g_wfl[DD*DD];
__device__ __nv_bfloat16 g_w1h[4*DD*DD], g_w1l[4*DD*DD];
__device__ __nv_bfloat16 g_w2h[4*DD*DD], g_w2l[4*DD*DD];

// ======================= LayerNorm -> bf16 hi/lo =======================
__global__ __launch_bounds__(256) void ln1024_split(
    const float* __restrict__ x, const float* __restrict__ g,
    const float* __restrict__ bt, __nv_bfloat16* __restrict__ yh,
    __nv_bfloat16* __restrict__ yl)
{
  int row = blockIdx.x;
  const float4* xr = (const float4*)(x + (size_t)row * 1024);
  float4 v = xr[threadIdx.x];
  float s = v.x + v.y + v.z + v.w;
  float q = v.x*v.x + v.y*v.y + v.z*v.z + v.w*v.w;
  #pragma unroll
  for (int off = 16; off; off >>= 1){
    s += __shfl_xor_sync(0xffffffffu, s, off);
    q += __shfl_xor_sync(0xffffffffu, q, off);
  }
  __shared__ float ss[8], qs[8];
  int w = threadIdx.x >> 5;
  if ((threadIdx.x & 31) == 0){ ss[w] = s; qs[w] = q; }
  __syncthreads();
  s = ss[0]+ss[1]+ss[2]+ss[3]+ss[4]+ss[5]+ss[6]+ss[7];
  q = qs[0]+qs[1]+qs[2]+qs[3]+qs[4]+qs[5]+qs[6]+qs[7];
  float mu   = s * (1.0f/1024.0f);
  float var  = q * (1.0f/1024.0f) - mu*mu;
  float rstd = rsqrtf(var + 1e-5f);
  int c = threadIdx.x * 4;
  float4 gg = *(const float4*)(g  + c);
  float4 bb = *(const float4*)(bt + c);
  float o0 = (v.x-mu)*rstd*gg.x + bb.x;
  float o1 = (v.y-mu)*rstd*gg.y + bb.y;
  float o2 = (v.z-mu)*rstd*gg.z + bb.z;
  float o3 = (v.w-mu)*rstd*gg.w + bb.w;
  __nv_bfloat16 h0=__float2bfloat16(o0), h1=__float2bfloat16(o1);
  __nv_bfloat16 h2=__float2bfloat16(o2), h3=__float2bfloat16(o3);
  __nv_bfloat162 ph0; ph0.x=h0; ph0.y=h1;
  __nv_bfloat162 ph1; ph1.x=h2; ph1.y=h3;
  __nv_bfloat162 pl0; pl0.x=__float2bfloat16(o0-__bfloat162float(h0));
                      pl0.y=__float2bfloat16(o1-__bfloat162float(h1));
  __nv_bfloat162 pl1; pl1.x=__float2bfloat16(o2-__bfloat162float(h2));
                      pl1.y=__float2bfloat16(o3-__bfloat162float(h3));
  size_t idx = (size_t)row*1024 + c;
  *(__nv_bfloat162*)(yh+idx)   = ph0; *(__nv_bfloat162*)(yh+idx+2) = ph1;
  *(__nv_bfloat162*)(yl+idx)   = pl0; *(__nv_bfloat162*)(yl+idx+2) = pl1;
}

// ======================= weight transpose + split =======================
__global__ void transp_split(const float* __restrict__ W,
                             __nv_bfloat16* __restrict__ Th,
                             __nv_bfloat16* __restrict__ Tl, int K, int N)
{
  __shared__ float t[32][33];
  int n0 = blockIdx.x*32, k0 = blockIdx.y*32;
  int tx = threadIdx.x, ty = threadIdx.y; // 32 x 8
  #pragma unroll
  for (int j = 0; j < 4; j++)
    t[ty+8*j][tx] = W[(size_t)(k0+ty+8*j)*N + n0+tx];
  __syncthreads();
  #pragma unroll
  for (int j = 0; j < 4; j++){
    float v = t[tx][ty+8*j];
    __nv_bfloat16 h = __float2bfloat16(v);
    size_t idx = (size_t)(n0+ty+8*j)*K + k0+tx;
    Th[idx] = h;
    Tl[idx] = __float2bfloat16(v - __bfloat162float(h));
  }
}

// ======================= split-bf16 GEMM: single K pass, hoisted frags ======
// CTA 128x256, 8 warps x 64x64. Stage holds Ah|Al|Bh|Bl (96KB); 2 stages.
// Per s-step: ALL 16 ldsm4 first, then 96 MMAs back-to-back.
__global__ __launch_bounds__(256, 1) void gemm_mma(
    const __nv_bfloat16* __restrict__ Ahi, const __nv_bfloat16* __restrict__ Alo,
    const __nv_bfloat16* __restrict__ Bhi, const __nv_bfloat16* __restrict__ Blo,
    const float* __restrict__ bias, const float* __restrict__ res,
    float* __restrict__ C, __nv_bfloat16* __restrict__ Chi,
    __nv_bfloat16* __restrict__ Clo,
    int M, int N, int K, int relu, int split)
{
  extern __shared__ __align__(1024) char smem[];
  const int tid = threadIdx.x, lane = tid & 31, wid = tid >> 5;
  const int m0 = blockIdx.y * 128, n0 = blockIdx.x * 256;
  const int wm = (wid >> 2) * 64, wn = (wid & 3) * 64;
  const uint32_t aS0 = s2u(smem);   // stage: Ah 16K | Al 16K | Bh 32K | Bl 32K = 96K

  const int nc = K >> 6;

  float acc[4][8][4];
  #pragma unroll
  for (int i = 0; i < 4; i++)
    #pragma unroll
    for (int j = 0; j < 8; j++)
      #pragma unroll
      for (int r = 0; r < 4; r++) acc[i][j][r] = 0.f;

  const int rowA = lane & 15;
  const int kbA  = (lane & 16) ? 16 : 0;
  const int rowB = (lane & 7) + ((lane & 16) ? 8 : 0);
  const int kbB  = (lane & 8) ? 16 : 0;

  #define ISSUE(c) do { \
    int _k0 = (c) << 6; \
    uint32_t _st = aS0 + ((c) & 1) * 98304; \
    _Pragma("unroll") \
    for (int _i = 0; _i < 4; _i++){ \
      int _gg = tid + 256*_i; int _r = _gg >> 3, _c = _gg & 7; \
      uint32_t _d = SWZ((uint32_t)(_r*128 + _c*16)); \
      const size_t _src = (size_t)(m0 + _r) * K + _k0 + _c*8; \
      cpasync16(_st + _d,         Ahi + _src); \
      cpasync16(_st + 16384 + _d, Alo + _src); \
    } \
    _Pragma("unroll") \
    for (int _i = 0; _i < 8; _i++){ \
      int _gg = tid + 256*_i; int _r = _gg >> 3, _c = _gg & 7; \
      uint32_t _d = SWZ((uint32_t)(_r*128 + _c*16)); \
      const size_t _src = (size_t)(n0 + _r) * K + _k0 + _c*8; \
      cpasync16(_st + 32768 + _d, Bhi + _src); \
      cpasync16(_st + 65536 + _d, Blo + _src); \
    } \
    CP_COMMIT(); \
  } while(0)

  ISSUE(0);
  for (int c = 0; c < nc; c++){
    CP_WAIT0();
    __syncthreads();
    if (c + 1 < nc) ISSUE(c + 1);
    const uint32_t st = aS0 + (c & 1) * 98304;
    #pragma unroll
    for (int s = 0; s < 4; s++){
      // ---- load ALL fragments for this s-step ----
      uint32_t ah[4][4], al[4][4], bh[4][4], bl[4][4];
      #pragma unroll
      for (int mi = 0; mi < 4; mi++){
        uint32_t off = SWZ((uint32_t)((wm + mi*16 + rowA)*128 + s*32 + kbA));
        ldsm4(ah[mi], st + off);
        ldsm4(al[mi], st + 16384 + off);
      }
      #pragma unroll
      for (int njp = 0; njp < 4; njp++){
        uint32_t off = SWZ((uint32_t)((wn + njp*16 + rowB)*128 + s*32 + kbB));
        ldsm4(bh[njp], st + 32768 + off);
        ldsm4(bl[njp], st + 65536 + off);
      }
      // ---- 96 MMAs back-to-back ----
      #pragma unroll
      for (int mi = 0; mi < 4; mi++)
        #pragma unroll
        for (int nj = 0; nj < 8; nj++)
          mma16816(acc[mi][nj], ah[mi], &bh[nj >> 1][(nj & 1) * 2]);
      #pragma unroll
      for (int mi = 0; mi < 4; mi++)
        #pragma unroll
        for (int nj = 0; nj < 8; nj++)
          mma16816(acc[mi][nj], ah[mi], &bl[nj >> 1][(nj & 1) * 2]);
      #pragma unroll
      for (int mi = 0; mi < 4; mi++)
        #pragma unroll
        for (int nj = 0; nj < 8; nj++)
          mma16816(acc[mi][nj], al[mi], &bh[nj >> 1][(nj & 1) * 2]);
    }
  }
  #undef ISSUE

  const int er = lane >> 2, ec = (lane & 3) * 2;
  #pragma unroll
  for (int mi = 0; mi < 4; mi++){
    #pragma unroll
    for (int half = 0; half < 2; half++){
      int row = m0 + wm + mi*16 + er + half*8;
      #pragma unroll
      for (int nj = 0; nj < 8; nj++){
        int col = n0 + wn + nj*8 + ec;
        float v0 = acc[mi][nj][half*2 + 0];
        float v1 = acc[mi][nj][half*2 + 1];
        if (bias){
          float2 bv = *(const float2*)(bias + col);
          v0 += bv.x; v1 += bv.y;
        }
        if (relu){ v0 = fmaxf(v0, 0.f); v1 = fmaxf(v1, 0.f); }
        if (res){
          float2 rv = *(const float2*)(res + (size_t)row*N + col);
          v0 += rv.x; v1 += rv.y;
        }
        size_t idx = (size_t)row*N + col;
        if (split){
          __nv_bfloat16 h0 = __float2bfloat16(v0), h1 = __float2bfloat16(v1);
          __nv_bfloat162 ph; ph.x = h0; ph.y = h1;
          __nv_bfloat162 pl;
          pl.x = __float2bfloat16(v0 - __bfloat162float(h0));
          pl.y = __float2bfloat16(v1 - __bfloat162float(h1));
          *(__nv_bfloat162*)(Chi + idx) = ph;
          *(__nv_bfloat162*)(Clo + idx) = pl;
        } else {
          float2 o; o.x = v0; o.y = v1;
          *(float2*)(C + idx) = o;
        }
      }
    }
  }
}

// ======================= flash attention via HMMA, split-bf16 =======================
// QKV fused buffer [rows, 3072]: Q at col 0, K at 1024, V at 2048 (head h -> +h*64).
__global__ __launch_bounds__(256, 1) void attn_mma(
    const __nv_bfloat16* __restrict__ QKVh, const __nv_bfloat16* __restrict__ QKVl,
    __nv_bfloat16* __restrict__ Oh, __nv_bfloat16* __restrict__ Ol)
{
  extern __shared__ __align__(1024) char smem[];
  const int tid = threadIdx.x, lane = tid & 31, warp = tid >> 5;
  const int b = blockIdx.z, h = blockIdx.y, q0 = blockIdx.x * 128;
  const size_t baseq = ((size_t)b * 2048) * 3072 + h * 64;
  const size_t baseo = ((size_t)b * 2048) * 1024 + h * 64;
  const uint32_t aQ = s2u(smem);
  const uint32_t aKV = aQ + 32768;
  const int wm = warp * 16;

  const int rowA = lane & 15;
  const int kbA  = (lane & 16) ? 16 : 0;
  const int rowB = (lane & 7) + ((lane & 16) ? 8 : 0);
  const int kbB  = (lane & 8) ? 16 : 0;
  const int kvr  = lane & 15;
  const int ncb  = (lane & 16) ? 8 : 0;

  // ---- preload Q ----
  #pragma unroll
  for (int i = 0; i < 4; i++){
    int gg = tid + 256*i;
    int r = gg >> 3, c = gg & 7;
    uint32_t d = SWZ((uint32_t)(r*128 + c*16));
    const size_t src = baseq + (size_t)(q0 + r) * 3072 + c*8;
    cpasync16(aQ + d, QKVh + src);
    cpasync16(aQ + 16384 + d, QKVl + src);
  }
  CP_COMMIT();

  #define ISSUEKV(j) do { \
    uint32_t _st = aKV + ((j) & 1) * 32768; \
    int _j0 = (j) * 64; \
    _Pragma("unroll") \
    for (int _i = 0; _i < 2; _i++){ \
      int _gg = tid + 256*_i; \
      int _r = _gg >> 3, _c = _gg & 7; \
      uint32_t _d = SWZ((uint32_t)(_r*128 + _c*16)); \
      const size_t _srcK = baseq + 1024 + (size_t)(_j0 + _r) * 3072 + _c*8; \
      const size_t _srcV = baseq + 2048 + (size_t)(_j0 + _r) * 3072 + _c*8; \
      cpasync16(_st + _d,         QKVh + _srcK); \
      cpasync16(_st + 8192 + _d,  QKVl + _srcK); \
      cpasync16(_st + 16384 + _d, QKVh + _srcV); \
      cpasync16(_st + 24576 + _d, QKVl + _srcV); \
    } \
    CP_COMMIT(); \
  } while(0)

  ISSUEKV(0);
  CP_WAIT1();
  __syncthreads();

  uint32_t qfh[4][4], qfl[4][4];
  #pragma unroll
  for (int s = 0; s < 4; s++){
    uint32_t off = SWZ((uint32_t)((wm + rowA)*128 + s*32 + kbA));
    ldsm4(qfh[s], aQ + off);
    ldsm4(qfl[s], aQ + 16384 + off);
  }

  float m0 = -1e30f, m1 = -1e30f, l0 = 0.f, l1 = 0.f;
  float oa[8][4];
  #pragma unroll
  for (int nb = 0; nb < 8; nb++)
    #pragma unroll
    for (int r = 0; r < 4; r++) oa[nb][r] = 0.f;

  #pragma unroll 1
  for (int jt = 0; jt < 32; jt++){
    if (jt + 1 < 32){ ISSUEKV(jt + 1); CP_WAIT1(); }
    else            { CP_WAIT0(); }
    __syncthreads();
    const uint32_t st = aKV + (jt & 1) * 32768;

    float sc[8][4];
    #pragma unroll
    for (int nb = 0; nb < 8; nb++)
      #pragma unroll
      for (int r = 0; r < 4; r++) sc[nb][r] = 0.f;
    #pragma unroll
    for (int s = 0; s < 4; s++){
      uint32_t kh[4][4], kl[4][4];
      #pragma unroll
      for (int g = 0; g < 4; g++){
        uint32_t off = SWZ((uint32_t)((g*16 + rowB)*128 + s*32 + kbB));
        ldsm4(kh[g], st + off);
        ldsm4(kl[g], st + 8192 + off);
      }
      #pragma unroll
      for (int g = 0; g < 4; g++){
        mma16816(sc[2*g],   qfh[s], kh[g]);
        mma16816(sc[2*g+1], qfh[s], kh[g] + 2);
        mma16816(sc[2*g],   qfl[s], kh[g]);
        mma16816(sc[2*g+1], qfl[s], kh[g] + 2);
        mma16816(sc[2*g],   qfh[s], kl[g]);
        mma16816(sc[2*g+1], qfh[s], kl[g] + 2);
      }
    }

    float mx0 = -1e30f, mx1 = -1e30f;
    #pragma unroll
    for (int nb = 0; nb < 8; nb++){
      sc[nb][0] *= 8.f; sc[nb][1] *= 8.f; sc[nb][2] *= 8.f; sc[nb][3] *= 8.f;
      mx0 = fmaxf(mx0, fmaxf(sc[nb][0], sc[nb][1]));
      mx1 = fmaxf(mx1, fmaxf(sc[nb][2], sc[nb][3]));
    }
    mx0 = fmaxf(mx0, __shfl_xor_sync(0xffffffffu, mx0, 1));
    mx0 = fmaxf(mx0, __shfl_xor_sync(0xffffffffu, mx0, 2));
    mx1 = fmaxf(mx1, __shfl_xor_sync(0xffffffffu, mx1, 1));
    mx1 = fmaxf(mx1, __shfl_xor_sync(0xffffffffu, mx1, 2));
    float nm0 = fmaxf(m0, mx0), nm1 = fmaxf(m1, mx1);
    float a0 = __expf(m0 - nm0), a1 = __expf(m1 - nm1);
    m0 = nm0; m1 = nm1;

    float rs0 = 0.f, rs1 = 0.f;
    uint32_t pfh[4][4], pfl[4][4];
    #pragma unroll
    for (int nb = 0; nb < 8; nb++){
      float p00 = __expf(sc[nb][0] - nm0), p01 = __expf(sc[nb][1] - nm0);
      float p10 = __expf(sc[nb][2] - nm1), p11 = __expf(sc[nb][3] - nm1);
      rs0 += p00 + p01; rs1 += p10 + p11;
      __nv_bfloat162 h0 = __floats2bfloat162_rn(p00, p01);
      __nv_bfloat162 h1 = __floats2bfloat162_rn(p10, p11);
      __nv_bfloat162 lo0 = __floats2bfloat162_rn(p00 - __bfloat162float(h0.x),
                                                 p01 - __bfloat162float(h0.y));
      __nv_bfloat162 lo1 = __floats2bfloat162_rn(p10 - __bfloat162float(h1.x),
                                                 p11 - __bfloat162float(h1.y));
      int j = nb >> 1, rq = (nb & 1) * 2;
      pfh[j][rq]   = *(uint32_t*)&h0;  pfh[j][rq+1] = *(uint32_t*)&h1;
      pfl[j][rq]   = *(uint32_t*)&lo0; pfl[j][rq+1] = *(uint32_t*)&lo1;
    }
    rs0 += __shfl_xor_sync(0xffffffffu, rs0, 1);
    rs0 += __shfl_xor_sync(0xffffffffu, rs0, 2);
    rs1 += __shfl_xor_sync(0xffffffffu, rs1, 1);
    rs1 += __shfl_xor_sync(0xffffffffu, rs1, 2);
    l0 = l0 * a0 + rs0; l1 = l1 * a1 + rs1;
    #pragma unroll
    for (int nb = 0; nb < 8; nb++){
      oa[nb][0] *= a0; oa[nb][1] *= a0; oa[nb][2] *= a1; oa[nb][3] *= a1;
    }

    #pragma unroll
    for (int s = 0; s < 4; s++){
      uint32_t vh[4][4], vl[4][4];
      #pragma unroll
      for (int g = 0; g < 4; g++){
        uint32_t off = SWZ((uint32_t)((s*16 + kvr)*128 + (g*16 + ncb)*2));
        ldsm4t(vh[g], st + 16384 + off);
        ldsm4t(vl[g], st + 24576 + off);
      }
      #pragma unroll
      for (int g = 0; g < 4; g++){
        mma16816(oa[2*g],   pfh[s], vh[g]);
        mma16816(oa[2*g+1], pfh[s], vh[g] + 2);
        mma16816(oa[2*g],   pfl[s], vh[g]);
        mma16816(oa[2*g+1], pfl[s], vh[g] + 2);
        mma16816(oa[2*g],   pfh[s], vl[g]);
        mma16816(oa[2*g+1], pfh[s], vl[g] + 2);
      }
    }
    __syncthreads();
  }

  const int er = lane >> 2, ec = (lane & 3) * 2;
  float i0 = 1.0f / l0, i1 = 1.0f / l1;
  const int r0 = q0 + wm + er;
  #pragma unroll
  for (int nb = 0; nb < 8; nb++){
    int col = nb*8 + ec;
    float v0 = oa[nb][0]*i0, v1 = oa[nb][1]*i0;
    float v2 = oa[nb][2]*i1, v3 = oa[nb][3]*i1;
    __nv_bfloat162 h0 = __floats2bfloat162_rn(v0, v1);
    __nv_bfloat162 h1 = __floats2bfloat162_rn(v2, v3);
    __nv_bfloat162 lo0 = __floats2bfloat162_rn(v0 - __bfloat162float(h0.x),
                                               v1 - __bfloat162float(h0.y));
    __nv_bfloat162 lo1 = __floats2bfloat162_rn(v2 - __bfloat162float(h1.x),
                                               v3 - __bfloat162float(h1.y));
    size_t i0x = baseo + (size_t)r0 * 1024 + col;
    size_t i1x = baseo + (size_t)(r0 + 8) * 1024 + col;
    *(__nv_bfloat162*)(Oh + i0x) = h0;
    *(__nv_bfloat162*)(Ol + i0x) = lo0;
    *(__nv_bfloat162*)(Oh + i1x) = h1;
    *(__nv_bfloat162*)(Ol + i1x) = lo1;
  }
  #undef ISSUEKV
}

// ======================= launch =======================
extern "C" void kernel_launch(void* const* d_in, const int* in_sizes, int n_in,
                              void* d_out, int out_size)
{
  (void)in_sizes; (void)n_in; (void)out_size;
  const float* x   = (const float*)d_in[0];
  const float* Wk  = (const float*)d_in[2];
  const float* Wq  = (const float*)d_in[3];
  const float* Wv  = (const float*)d_in[4];
  const float* Wfc = (const float*)d_in[5];
  const float* bfc = (const float*)d_in[6];
  const float* g1  = (const float*)d_in[7];
  const float* b1  = (const float*)d_in[8];
  const float* g2  = (const float*)d_in[9];
  const float* b2  = (const float*)d_in[10];
  const float* W1  = (const float*)d_in[11];
  const float* bf1 = (const float*)d_in[12];
  const float* W2  = (const float*)d_in[13];
  const float* bf2 = (const float*)d_in[14];
  float* out = (float*)d_out;

  __nv_bfloat16 *xlh,*xll,*qkvh,*qkvl,*oh,*ol,*hh,*hl;
  __nv_bfloat16 *wqkvh,*wqkvl,*wfh,*wfl,*w1h,*w1l,*w2h,*w2l;
  float *x2;
  cudaGetSymbolAddress((void**)&xlh, g_xlh); cudaGetSymbolAddress((void**)&xll, g_xll);
  cudaGetSymbolAddress((void**)&qkvh, g_qkvh); cudaGetSymbolAddress((void**)&qkvl, g_qkvl);
  cudaGetSymbolAddress((void**)&oh, g_oh); cudaGetSymbolAddress((void**)&ol, g_ol);
  cudaGetSymbolAddress((void**)&x2, g_x2);
  cudaGetSymbolAddress((void**)&hh, g_hh); cudaGetSymbolAddress((void**)&hl, g_hl);
  cudaGetSymbolAddress((void**)&wqkvh, g_wqkvh); cudaGetSymbolAddress((void**)&wqkvl, g_wqkvl);
  cudaGetSymbolAddress((void**)&wfh, g_wfh); cudaGetSymbolAddress((void**)&wfl, g_wfl);
  cudaGetSymbolAddress((void**)&w1h, g_w1h); cudaGetSymbolAddress((void**)&w1l, g_w1l);
  cudaGetSymbolAddress((void**)&w2h, g_w2h); cudaGetSymbolAddress((void**)&w2l, g_w2l);

  static int smem_set = 0;
  if (!smem_set){
    cudaFuncSetAttribute(gemm_mma, cudaFuncAttributeMaxDynamicSharedMemorySize, 196608);
    cudaFuncSetAttribute(attn_mma, cudaFuncAttributeMaxDynamicSharedMemorySize, 98304);
    smem_set = 1;
  }

  const int M = 8192, D = 1024;
  const int GSM = 196608;
  const int ASM = 98304;
  dim3 tb(32, 8);
  dim3 tD(D/32, D/32);

  transp_split<<<tD, tb>>>(Wq, wqkvh,           wqkvl,           D, D);
  transp_split<<<tD, tb>>>(Wk, wqkvh + DD*DD,   wqkvl + DD*DD,   D, D);
  transp_split<<<tD, tb>>>(Wv, wqkvh + 2*DD*DD, wqkvl + 2*DD*DD, D, D);
  transp_split<<<tD, tb>>>(Wfc, wfh, wfl, D, D);
  transp_split<<<dim3(4*D/32, D/32), tb>>>(W1, w1h, w1l, D, 4*D);
  transp_split<<<dim3(D/32, 4*D/32), tb>>>(W2, w2h, w2l, 4*D, D);

  dim3 gQKV(3*D/256, M/128);   // (12, 64)
  dim3 gD(D/256, M/128);       // (4, 64)
  dim3 gF(4*D/256, M/128);     // (16, 64)

  ln1024_split<<<M, 256>>>(x, g1, b1, xlh, xll);
  gemm_mma<<<gQKV, 256, GSM>>>(xlh, xll, wqkvh, wqkvl, nullptr, nullptr, nullptr,
                               qkvh, qkvl, M, 3*D, D, 0, 1);
  attn_mma<<<dim3(16, 16, 4), 256, ASM>>>(qkvh, qkvl, oh, ol);
  gemm_mma<<<gD, 256, GSM>>>(oh, ol, wfh, wfl, bfc, x, x2, nullptr, nullptr,
                             M, D, D, 0, 0);
  ln1024_split<<<M, 256>>>(x2, g2, b2, xlh, xll);
  gemm_mma<<<gF, 256, GSM>>>(xlh, xll, w1h, w1l, bf1, nullptr, nullptr, hh, hl,
                             M, 4*D, D, 1, 1);
  gemm_mma<<<gD, 256, GSM>>>(hh, hl, w2h, w2l, bf2, x2, out, nullptr, nullptr,
                             M, D, 4*D, 0, 0);
}

// round 9
// speedup vs baseline: 3.6981x; 1.0155x over previous
#include <cuda_runtime.h>
#include <cuda_bf16.h>
#include <cstdint>

typedef unsigned long long ull;

// ---- PTX helpers (portable sm_80+) ----
__device__ __forceinline__ uint32_t s2u(const void* p){
  uint32_t a; asm("{ .reg .u64 t; cvta.to.shared.u64 t, %1; cvt.u32.u64 %0, t; }"
                  : "=r"(a) : "l"(p));
  return a;
}
__device__ __forceinline__ void ldsm4(uint32_t* r, uint32_t a){
  asm volatile("ldmatrix.sync.aligned.m8n8.x4.shared.b16 {%0,%1,%2,%3}, [%4];"
               : "=r"(r[0]), "=r"(r[1]), "=r"(r[2]), "=r"(r[3]) : "r"(a));
}
__device__ __forceinline__ void ldsm4t(uint32_t* r, uint32_t a){
  asm volatile("ldmatrix.sync.aligned.m8n8.x4.trans.shared.b16 {%0,%1,%2,%3}, [%4];"
               : "=r"(r[0]), "=r"(r[1]), "=r"(r[2]), "=r"(r[3]) : "r"(a));
}
__device__ __forceinline__ void mma16816(float* d, const uint32_t* a, const uint32_t* b){
  asm volatile(
    "mma.sync.aligned.m16n8k16.row.col.f32.bf16.bf16.f32 "
    "{%0,%1,%2,%3}, {%4,%5,%6,%7}, {%8,%9}, {%0,%1,%2,%3};"
    : "+f"(d[0]), "+f"(d[1]), "+f"(d[2]), "+f"(d[3])
    : "r"(a[0]), "r"(a[1]), "r"(a[2]), "r"(a[3]), "r"(b[0]), "r"(b[1]));
}
__device__ __forceinline__ void cpasync16(uint32_t dst, const void* src){
  asm volatile("cp.async.cg.shared.global [%0], [%1], 16;" :: "r"(dst), "l"(src) : "memory");
}
__device__ __forceinline__ float ex2f(float x){
  float y; asm("ex2.approx.ftz.f32 %0, %1;" : "=f"(y) : "f"(x)); return y;
}
#define CP_COMMIT() asm volatile("cp.async.commit_group;" ::: "memory")
#define CP_WAIT1()  asm volatile("cp.async.wait_group 1;" ::: "memory")
#define CP_WAIT0()  asm volatile("cp.async.wait_group 0;" ::: "memory")

#define SWZ(o) ((o) ^ (((o) >> 3) & 0x70))
#define C8L2E 11.541560327111707f   // 8 * log2(e)

// ======================= scratch (device globals) =======================
#define MR 8192
#define DD 1024
__device__ __nv_bfloat16 g_xlh[MR*DD], g_xll[MR*DD];
__device__ __nv_bfloat16 g_qkvh[MR*3*DD], g_qkvl[MR*3*DD];
__device__ __nv_bfloat16 g_oh[MR*DD], g_ol[MR*DD];
__device__ float g_x2[MR*DD];
__device__ __nv_bfloat16 g_hh[MR*4*DD], g_hl[MR*4*DD];
__device__ __nv_bfloat16 g_wqkvh[3*DD*DD], g_wqkvl[3*DD*DD];
__device__ __nv_bfloat16 g_wfh[DD*DD], g_wfl[DD*DD];
__device__ __nv_bfloat16 g_w1h[4*DD*DD], g_w1l[4*DD*DD];
__device__ __nv_bfloat16 g_w2h[4*DD*DD], g_w2l[4*DD*DD];

// ======================= LayerNorm -> bf16 hi/lo =======================
__global__ __launch_bounds__(256) void ln1024_split(
    const float* __restrict__ x, const float* __restrict__ g,
    const float* __restrict__ bt, __nv_bfloat16* __restrict__ yh,
    __nv_bfloat16* __restrict__ yl)
{
  int row = blockIdx.x;
  const float4* xr = (const float4*)(x + (size_t)row * 1024);
  float4 v = xr[threadIdx.x];
  float s = v.x + v.y + v.z + v.w;
  float q = v.x*v.x + v.y*v.y + v.z*v.z + v.w*v.w;
  #pragma unroll
  for (int off = 16; off; off >>= 1){
    s += __shfl_xor_sync(0xffffffffu, s, off);
    q += __shfl_xor_sync(0xffffffffu, q, off);
  }
  __shared__ float ss[8], qs[8];
  int w = threadIdx.x >> 5;
  if ((threadIdx.x & 31) == 0){ ss[w] = s; qs[w] = q; }
  __syncthreads();
  s = ss[0]+ss[1]+ss[2]+ss[3]+ss[4]+ss[5]+ss[6]+ss[7];
  q = qs[0]+qs[1]+qs[2]+qs[3]+qs[4]+qs[5]+qs[6]+qs[7];
  float mu   = s * (1.0f/1024.0f);
  float var  = q * (1.0f/1024.0f) - mu*mu;
  float rstd = rsqrtf(var + 1e-5f);
  int c = threadIdx.x * 4;
  float4 gg = *(const float4*)(g  + c);
  float4 bb = *(const float4*)(bt + c);
  float o0 = (v.x-mu)*rstd*gg.x + bb.x;
  float o1 = (v.y-mu)*rstd*gg.y + bb.y;
  float o2 = (v.z-mu)*rstd*gg.z + bb.z;
  float o3 = (v.w-mu)*rstd*gg.w + bb.w;
  __nv_bfloat16 h0=__float2bfloat16(o0), h1=__float2bfloat16(o1);
  __nv_bfloat16 h2=__float2bfloat16(o2), h3=__float2bfloat16(o3);
  __nv_bfloat162 ph0; ph0.x=h0; ph0.y=h1;
  __nv_bfloat162 ph1; ph1.x=h2; ph1.y=h3;
  __nv_bfloat162 pl0; pl0.x=__float2bfloat16(o0-__bfloat162float(h0));
                      pl0.y=__float2bfloat16(o1-__bfloat162float(h1));
  __nv_bfloat162 pl1; pl1.x=__float2bfloat16(o2-__bfloat162float(h2));
                      pl1.y=__float2bfloat16(o3-__bfloat162float(h3));
  size_t idx = (size_t)row*1024 + c;
  *(__nv_bfloat162*)(yh+idx)   = ph0; *(__nv_bfloat162*)(yh+idx+2) = ph1;
  *(__nv_bfloat162*)(yl+idx)   = pl0; *(__nv_bfloat162*)(yl+idx+2) = pl1;
}

// ======================= all weight transposes in ONE kernel =======================
__global__ void transp_split_all(
    const float* __restrict__ Wq, const float* __restrict__ Wk,
    const float* __restrict__ Wv, const float* __restrict__ Wfc,
    const float* __restrict__ W1, const float* __restrict__ W2,
    __nv_bfloat16* __restrict__ qkvh, __nv_bfloat16* __restrict__ qkvl,
    __nv_bfloat16* __restrict__ wfh,  __nv_bfloat16* __restrict__ wfl,
    __nv_bfloat16* __restrict__ w1h,  __nv_bfloat16* __restrict__ w1l,
    __nv_bfloat16* __restrict__ w2h,  __nv_bfloat16* __restrict__ w2l)
{
  int i = blockIdx.x;
  const float* W; __nv_bfloat16 *Th, *Tl; int K, N;
  if (i < 4096){
    K = 1024; N = 1024;
    int seg = i >> 10; i &= 1023;
    if      (seg == 0){ W = Wq;  Th = qkvh;              Tl = qkvl; }
    else if (seg == 1){ W = Wk;  Th = qkvh + 1048576;    Tl = qkvl + 1048576; }
    else if (seg == 2){ W = Wv;  Th = qkvh + 2097152;    Tl = qkvl + 2097152; }
    else              { W = Wfc; Th = wfh;               Tl = wfl; }
  } else if (i < 8192){ W = W1; Th = w1h; Tl = w1l; K = 1024; N = 4096; i -= 4096; }
  else                { W = W2; Th = w2h; Tl = w2l; K = 4096; N = 1024; i -= 8192; }
  int ntx = N >> 5;
  int n0 = (i % ntx) * 32, k0 = (i / ntx) * 32;

  __shared__ float t[32][33];
  int tx = threadIdx.x, ty = threadIdx.y; // 32 x 8
  #pragma unroll
  for (int j = 0; j < 4; j++)
    t[ty+8*j][tx] = W[(size_t)(k0+ty+8*j)*N + n0+tx];
  __syncthreads();
  #pragma unroll
  for (int j = 0; j < 4; j++){
    float v = t[tx][ty+8*j];
    __nv_bfloat16 h = __float2bfloat16(v);
    size_t idx = (size_t)(n0+ty+8*j)*K + k0+tx;
    Th[idx] = h;
    Tl[idx] = __float2bfloat16(v - __bfloat162float(h));
  }
}

// ======================= split-bf16 GEMM: early-issue DMA pipeline ======
// CTA 128x256, 8 warps x 64x64. Stage Ah|Al|Bh|Bl (96KB); 2 stages.
// Order per chunk: sync -> ISSUE(c+1) -> WAIT1 -> sync -> compute.
__global__ __launch_bounds__(256, 1) void gemm_mma(
    const __nv_bfloat16* __restrict__ Ahi, const __nv_bfloat16* __restrict__ Alo,
    const __nv_bfloat16* __restrict__ Bhi, const __nv_bfloat16* __restrict__ Blo,
    const float* __restrict__ bias, const float* __restrict__ res,
    float* __restrict__ C, __nv_bfloat16* __restrict__ Chi,
    __nv_bfloat16* __restrict__ Clo,
    int M, int N, int K, int relu, int split)
{
  extern __shared__ __align__(1024) char smem[];
  const int tid = threadIdx.x, lane = tid & 31, wid = tid >> 5;
  const int m0 = blockIdx.y * 128, n0 = blockIdx.x * 256;
  const int wm = (wid >> 2) * 64, wn = (wid & 3) * 64;
  const uint32_t aS0 = s2u(smem);

  const int nc = K >> 6;

  float acc[4][8][4];
  #pragma unroll
  for (int i = 0; i < 4; i++)
    #pragma unroll
    for (int j = 0; j < 8; j++)
      #pragma unroll
      for (int r = 0; r < 4; r++) acc[i][j][r] = 0.f;

  const int rowA = lane & 15;
  const int kbA  = (lane & 16) ? 16 : 0;
  const int rowB = (lane & 7) + ((lane & 16) ? 8 : 0);
  const int kbB  = (lane & 8) ? 16 : 0;

  #define ISSUE(c) do { \
    int _k0 = (c) << 6; \
    uint32_t _st = aS0 + ((c) & 1) * 98304; \
    _Pragma("unroll") \
    for (int _i = 0; _i < 4; _i++){ \
      int _gg = tid + 256*_i; int _r = _gg >> 3, _c = _gg & 7; \
      uint32_t _d = SWZ((uint32_t)(_r*128 + _c*16)); \
      const size_t _src = (size_t)(m0 + _r) * K + _k0 + _c*8; \
      cpasync16(_st + _d,         Ahi + _src); \
      cpasync16(_st + 16384 + _d, Alo + _src); \
    } \
    _Pragma("unroll") \
    for (int _i = 0; _i < 8; _i++){ \
      int _gg = tid + 256*_i; int _r = _gg >> 3, _c = _gg & 7; \
      uint32_t _d = SWZ((uint32_t)(_r*128 + _c*16)); \
      const size_t _src = (size_t)(n0 + _r) * K + _k0 + _c*8; \
      cpasync16(_st + 32768 + _d, Bhi + _src); \
      cpasync16(_st + 65536 + _d, Blo + _src); \
    } \
    CP_COMMIT(); \
  } while(0)

  ISSUE(0);
  for (int c = 0; c < nc; c++){
    __syncthreads();                       // stage (c+1)&1 free (compute c-1 done)
    if (c + 1 < nc){ ISSUE(c + 1); CP_WAIT1(); }
    else           { CP_WAIT0(); }
    __syncthreads();                       // group c visible to all threads
    const uint32_t st = aS0 + (c & 1) * 98304;
    #pragma unroll
    for (int s = 0; s < 4; s++){
      uint32_t ah[4][4], al[4][4], bh[4][4], bl[4][4];
      #pragma unroll
      for (int mi = 0; mi < 4; mi++){
        uint32_t off = SWZ((uint32_t)((wm + mi*16 + rowA)*128 + s*32 + kbA));
        ldsm4(ah[mi], st + off);
        ldsm4(al[mi], st + 16384 + off);
      }
      #pragma unroll
      for (int njp = 0; njp < 4; njp++){
        uint32_t off = SWZ((uint32_t)((wn + njp*16 + rowB)*128 + s*32 + kbB));
        ldsm4(bh[njp], st + 32768 + off);
        ldsm4(bl[njp], st + 65536 + off);
      }
      #pragma unroll
      for (int mi = 0; mi < 4; mi++)
        #pragma unroll
        for (int nj = 0; nj < 8; nj++)
          mma16816(acc[mi][nj], ah[mi], &bh[nj >> 1][(nj & 1) * 2]);
      #pragma unroll
      for (int mi = 0; mi < 4; mi++)
        #pragma unroll
        for (int nj = 0; nj < 8; nj++)
          mma16816(acc[mi][nj], ah[mi], &bl[nj >> 1][(nj & 1) * 2]);
      #pragma unroll
      for (int mi = 0; mi < 4; mi++)
        #pragma unroll
        for (int nj = 0; nj < 8; nj++)
          mma16816(acc[mi][nj], al[mi], &bh[nj >> 1][(nj & 1) * 2]);
    }
  }
  #undef ISSUE

  const int er = lane >> 2, ec = (lane & 3) * 2;
  #pragma unroll
  for (int mi = 0; mi < 4; mi++){
    #pragma unroll
    for (int half = 0; half < 2; half++){
      int row = m0 + wm + mi*16 + er + half*8;
      #pragma unroll
      for (int nj = 0; nj < 8; nj++){
        int col = n0 + wn + nj*8 + ec;
        float v0 = acc[mi][nj][half*2 + 0];
        float v1 = acc[mi][nj][half*2 + 1];
        if (bias){
          float2 bv = *(const float2*)(bias + col);
          v0 += bv.x; v1 += bv.y;
        }
        if (relu){ v0 = fmaxf(v0, 0.f); v1 = fmaxf(v1, 0.f); }
        if (res){
          float2 rv = *(const float2*)(res + (size_t)row*N + col);
          v0 += rv.x; v1 += rv.y;
        }
        size_t idx = (size_t)row*N + col;
        if (split){
          __nv_bfloat16 h0 = __float2bfloat16(v0), h1 = __float2bfloat16(v1);
          __nv_bfloat162 ph; ph.x = h0; ph.y = h1;
          __nv_bfloat162 pl;
          pl.x = __float2bfloat16(v0 - __bfloat162float(h0));
          pl.y = __float2bfloat16(v1 - __bfloat162float(h1));
          *(__nv_bfloat162*)(Chi + idx) = ph;
          *(__nv_bfloat162*)(Clo + idx) = pl;
        } else {
          float2 o; o.x = v0; o.y = v1;
          *(float2*)(C + idx) = o;
        }
      }
    }
  }
}

// ======================= flash attention via HMMA, split-bf16 =======================
// QKV fused buffer [rows, 3072]. 3-stage KV ring, ONE sync per iteration.
// Softmax on raw scores: p = ex2((sc - m) * 8*log2e).
__global__ __launch_bounds__(256, 1) void attn_mma(
    const __nv_bfloat16* __restrict__ QKVh, const __nv_bfloat16* __restrict__ QKVl,
    __nv_bfloat16* __restrict__ Oh, __nv_bfloat16* __restrict__ Ol)
{
  extern __shared__ __align__(1024) char smem[];
  const int tid = threadIdx.x, lane = tid & 31, warp = tid >> 5;
  const int b = blockIdx.z, h = blockIdx.y, q0 = blockIdx.x * 128;
  const size_t baseq = ((size_t)b * 2048) * 3072 + h * 64;
  const size_t baseo = ((size_t)b * 2048) * 1024 + h * 64;
  const uint32_t aQ = s2u(smem);
  const uint32_t aKV = aQ + 32768;       // 3 stages x 32KB
  const int wm = warp * 16;

  const int rowA = lane & 15;
  const int kbA  = (lane & 16) ? 16 : 0;
  const int rowB = (lane & 7) + ((lane & 16) ? 8 : 0);
  const int kbB  = (lane & 8) ? 16 : 0;
  const int kvr  = lane & 15;
  const int ncb  = (lane & 16) ? 8 : 0;

  // ---- preload Q (group 0) ----
  #pragma unroll
  for (int i = 0; i < 4; i++){
    int gg = tid + 256*i;
    int r = gg >> 3, c = gg & 7;
    uint32_t d = SWZ((uint32_t)(r*128 + c*16));
    const size_t src = baseq + (size_t)(q0 + r) * 3072 + c*8;
    cpasync16(aQ + d, QKVh + src);
    cpasync16(aQ + 16384 + d, QKVl + src);
  }
  CP_COMMIT();

  #define ISSUEKV(j) do { \
    uint32_t _st = aKV + ((j) % 3) * 32768; \
    int _j0 = (j) * 64; \
    _Pragma("unroll") \
    for (int _i = 0; _i < 2; _i++){ \
      int _gg = tid + 256*_i; \
      int _r = _gg >> 3, _c = _gg & 7; \
      uint32_t _d = SWZ((uint32_t)(_r*128 + _c*16)); \
      const size_t _srcK = baseq + 1024 + (size_t)(_j0 + _r) * 3072 + _c*8; \
      const size_t _srcV = baseq + 2048 + (size_t)(_j0 + _r) * 3072 + _c*8; \
      cpasync16(_st + _d,         QKVh + _srcK); \
      cpasync16(_st + 8192 + _d,  QKVl + _srcK); \
      cpasync16(_st + 16384 + _d, QKVh + _srcV); \
      cpasync16(_st + 24576 + _d, QKVl + _srcV); \
    } \
    CP_COMMIT(); \
  } while(0)

  ISSUEKV(0);

  uint32_t qfh[4][4], qfl[4][4];
  float m0 = -1e30f, m1 = -1e30f, l0 = 0.f, l1 = 0.f;
  float oa[8][4];
  #pragma unroll
  for (int nb = 0; nb < 8; nb++)
    #pragma unroll
    for (int r = 0; r < 4; r++) oa[nb][r] = 0.f;

  #pragma unroll 1
  for (int jt = 0; jt < 32; jt++){
    if (jt + 1 < 32){ ISSUEKV(jt + 1); CP_WAIT1(); }
    else            { CP_WAIT0(); }
    __syncthreads();
    const uint32_t st = aKV + (jt % 3) * 32768;

    if (jt == 0){
      #pragma unroll
      for (int s = 0; s < 4; s++){
        uint32_t off = SWZ((uint32_t)((wm + rowA)*128 + s*32 + kbA));
        ldsm4(qfh[s], aQ + off);
        ldsm4(qfl[s], aQ + 16384 + off);
      }
    }

    float sc[8][4];
    #pragma unroll
    for (int nb = 0; nb < 8; nb++)
      #pragma unroll
      for (int r = 0; r < 4; r++) sc[nb][r] = 0.f;
    #pragma unroll
    for (int s = 0; s < 4; s++){
      uint32_t kh[4][4], kl[4][4];
      #pragma unroll
      for (int g = 0; g < 4; g++){
        uint32_t off = SWZ((uint32_t)((g*16 + rowB)*128 + s*32 + kbB));
        ldsm4(kh[g], st + off);
        ldsm4(kl[g], st + 8192 + off);
      }
      #pragma unroll
      for (int g = 0; g < 4; g++){
        mma16816(sc[2*g],   qfh[s], kh[g]);
        mma16816(sc[2*g+1], qfh[s], kh[g] + 2);
        mma16816(sc[2*g],   qfl[s], kh[g]);
        mma16816(sc[2*g+1], qfl[s], kh[g] + 2);
        mma16816(sc[2*g],   qfh[s], kl[g]);
        mma16816(sc[2*g+1], qfh[s], kl[g] + 2);
      }
    }

    // ---- online softmax on raw scores (x8, log2e folded into one FMA) ----
    float mx0 = -1e30f, mx1 = -1e30f;
    #pragma unroll
    for (int nb = 0; nb < 8; nb++){
      mx0 = fmaxf(mx0, fmaxf(sc[nb][0], sc[nb][1]));
      mx1 = fmaxf(mx1, fmaxf(sc[nb][2], sc[nb][3]));
    }
    mx0 = fmaxf(mx0, __shfl_xor_sync(0xffffffffu, mx0, 1));
    mx0 = fmaxf(mx0, __shfl_xor_sync(0xffffffffu, mx0, 2));
    mx1 = fmaxf(mx1, __shfl_xor_sync(0xffffffffu, mx1, 1));
    mx1 = fmaxf(mx1, __shfl_xor_sync(0xffffffffu, mx1, 2));
    float nm0 = fmaxf(m0, mx0), nm1 = fmaxf(m1, mx1);
    float a0 = ex2f((m0 - nm0) * C8L2E), a1 = ex2f((m1 - nm1) * C8L2E);
    m0 = nm0; m1 = nm1;
    float c0 = nm0 * C8L2E, c1 = nm1 * C8L2E;

    float rs0 = 0.f, rs1 = 0.f;
    uint32_t pfh[4][4], pfl[4][4];
    #pragma unroll
    for (int nb = 0; nb < 8; nb++){
      float p00 = ex2f(fmaf(sc[nb][0], C8L2E, -c0));
      float p01 = ex2f(fmaf(sc[nb][1], C8L2E, -c0));
      float p10 = ex2f(fmaf(sc[nb][2], C8L2E, -c1));
      float p11 = ex2f(fmaf(sc[nb][3], C8L2E, -c1));
      rs0 += p00 + p01; rs1 += p10 + p11;
      __nv_bfloat162 h0 = __floats2bfloat162_rn(p00, p01);
      __nv_bfloat162 h1 = __floats2bfloat162_rn(p10, p11);
      __nv_bfloat162 lo0 = __floats2bfloat162_rn(p00 - __bfloat162float(h0.x),
                                                 p01 - __bfloat162float(h0.y));
      __nv_bfloat162 lo1 = __floats2bfloat162_rn(p10 - __bfloat162float(h1.x),
                                                 p11 - __bfloat162float(h1.y));
      int j = nb >> 1, rq = (nb & 1) * 2;
      pfh[j][rq]   = *(uint32_t*)&h0;  pfh[j][rq+1] = *(uint32_t*)&h1;
      pfl[j][rq]   = *(uint32_t*)&lo0; pfl[j][rq+1] = *(uint32_t*)&lo1;
    }
    rs0 += __shfl_xor_sync(0xffffffffu, rs0, 1);
    rs0 += __shfl_xor_sync(0xffffffffu, rs0, 2);
    rs1 += __shfl_xor_sync(0xffffffffu, rs1, 1);
    rs1 += __shfl_xor_sync(0xffffffffu, rs1, 2);
    l0 = l0 * a0 + rs0; l1 = l1 * a1 + rs1;
    #pragma unroll
    for (int nb = 0; nb < 8; nb++){
      oa[nb][0] *= a0; oa[nb][1] *= a0; oa[nb][2] *= a1; oa[nb][3] *= a1;
    }

    #pragma unroll
    for (int s = 0; s < 4; s++){
      uint32_t vh[4][4], vl[4][4];
      #pragma unroll
      for (int g = 0; g < 4; g++){
        uint32_t off = SWZ((uint32_t)((s*16 + kvr)*128 + (g*16 + ncb)*2));
        ldsm4t(vh[g], st + 16384 + off);
        ldsm4t(vl[g], st + 24576 + off);
      }
      #pragma unroll
      for (int g = 0; g < 4; g++){
        mma16816(oa[2*g],   pfh[s], vh[g]);
        mma16816(oa[2*g+1], pfh[s], vh[g] + 2);
        mma16816(oa[2*g],   pfl[s], vh[g]);
        mma16816(oa[2*g+1], pfl[s], vh[g] + 2);
        mma16816(oa[2*g],   pfh[s], vl[g]);
        mma16816(oa[2*g+1], pfh[s], vl[g] + 2);
      }
    }
  }

  const int er = lane >> 2, ec = (lane & 3) * 2;
  float i0 = 1.0f / l0, i1 = 1.0f / l1;
  const int r0 = q0 + wm + er;
  #pragma unroll
  for (int nb = 0; nb < 8; nb++){
    int col = nb*8 + ec;
    float v0 = oa[nb][0]*i0, v1 = oa[nb][1]*i0;
    float v2 = oa[nb][2]*i1, v3 = oa[nb][3]*i1;
    __nv_bfloat162 h0 = __floats2bfloat162_rn(v0, v1);
    __nv_bfloat162 h1 = __floats2bfloat162_rn(v2, v3);
    __nv_bfloat162 lo0 = __floats2bfloat162_rn(v0 - __bfloat162float(h0.x),
                                               v1 - __bfloat162float(h0.y));
    __nv_bfloat162 lo1 = __floats2bfloat162_rn(v2 - __bfloat162float(h1.x),
                                               v3 - __bfloat162float(h1.y));
    size_t i0x = baseo + (size_t)r0 * 1024 + col;
    size_t i1x = baseo + (size_t)(r0 + 8) * 1024 + col;
    *(__nv_bfloat162*)(Oh + i0x) = h0;
    *(__nv_bfloat162*)(Ol + i0x) = lo0;
    *(__nv_bfloat162*)(Oh + i1x) = h1;
    *(__nv_bfloat162*)(Ol + i1x) = lo1;
  }
  #undef ISSUEKV
}

// ======================= launch =======================
extern "C" void kernel_launch(void* const* d_in, const int* in_sizes, int n_in,
                              void* d_out, int out_size)
{
  (void)in_sizes; (void)n_in; (void)out_size;
  const float* x   = (const float*)d_in[0];
  const float* Wk  = (const float*)d_in[2];
  const float* Wq  = (const float*)d_in[3];
  const float* Wv  = (const float*)d_in[4];
  const float* Wfc = (const float*)d_in[5];
  const float* bfc = (const float*)d_in[6];
  const float* g1  = (const float*)d_in[7];
  const float* b1  = (const float*)d_in[8];
  const float* g2  = (const float*)d_in[9];
  const float* b2  = (const float*)d_in[10];
  const float* W1  = (const float*)d_in[11];
  const float* bf1 = (const float*)d_in[12];
  const float* W2  = (const float*)d_in[13];
  const float* bf2 = (const float*)d_in[14];
  float* out = (float*)d_out;

  __nv_bfloat16 *xlh,*xll,*qkvh,*qkvl,*oh,*ol,*hh,*hl;
  __nv_bfloat16 *wqkvh,*wqkvl,*wfh,*wfl,*w1h,*w1l,*w2h,*w2l;
  float *x2;
  cudaGetSymbolAddress((void**)&xlh, g_xlh); cudaGetSymbolAddress((void**)&xll, g_xll);
  cudaGetSymbolAddress((void**)&qkvh, g_qkvh); cudaGetSymbolAddress((void**)&qkvl, g_qkvl);
  cudaGetSymbolAddress((void**)&oh, g_oh); cudaGetSymbolAddress((void**)&ol, g_ol);
  cudaGetSymbolAddress((void**)&x2, g_x2);
  cudaGetSymbolAddress((void**)&hh, g_hh); cudaGetSymbolAddress((void**)&hl, g_hl);
  cudaGetSymbolAddress((void**)&wqkvh, g_wqkvh); cudaGetSymbolAddress((void**)&wqkvl, g_wqkvl);
  cudaGetSymbolAddress((void**)&wfh, g_wfh); cudaGetSymbolAddress((void**)&wfl, g_wfl);
  cudaGetSymbolAddress((void**)&w1h, g_w1h); cudaGetSymbolAddress((void**)&w1l, g_w1l);
  cudaGetSymbolAddress((void**)&w2h, g_w2h); cudaGetSymbolAddress((void**)&w2l, g_w2l);

  static int smem_set = 0;
  if (!smem_set){
    cudaFuncSetAttribute(gemm_mma, cudaFuncAttributeMaxDynamicSharedMemorySize, 196608);
    cudaFuncSetAttribute(attn_mma, cudaFuncAttributeMaxDynamicSharedMemorySize, 131072);
    smem_set = 1;
  }

  const int M = 8192, D = 1024;
  const int GSM = 196608;
  const int ASM = 131072;   // Q 32KB + 3x32KB KV ring
  dim3 tb(32, 8);

  transp_split_all<<<12288, tb>>>(Wq, Wk, Wv, Wfc, W1, W2,
                                  wqkvh, wqkvl, wfh, wfl, w1h, w1l, w2h, w2l);

  dim3 gQKV(3*D/256, M/128);   // (12, 64)
  dim3 gD(D/256, M/128);       // (4, 64)
  dim3 gF(4*D/256, M/128);     // (16, 64)

  ln1024_split<<<M, 256>>>(x, g1, b1, xlh, xll);
  gemm_mma<<<gQKV, 256, GSM>>>(xlh, xll, wqkvh, wqkvl, nullptr, nullptr, nullptr,
                               qkvh, qkvl, M, 3*D, D, 0, 1);
  attn_mma<<<dim3(16, 16, 4), 256, ASM>>>(qkvh, qkvl, oh, ol);
  gemm_mma<<<gD, 256, GSM>>>(oh, ol, wfh, wfl, bfc, x, x2, nullptr, nullptr,
                             M, D, D, 0, 0);
  ln1024_split<<<M, 256>>>(x2, g2, b2, xlh, xll);
  gemm_mma<<<gF, 256, GSM>>>(xlh, xll, w1h, w1l, bf1, nullptr, nullptr, hh, hl,
                             M, 4*D, D, 1, 1);
  gemm_mma<<<gD, 256, GSM>>>(hh, hl, w2h, w2l, bf2, x2, out, nullptr, nullptr,
                             M, D, 4*D, 0, 0);
}